// round 1
// baseline (speedup 1.0000x reference)
#include <cuda_runtime.h>
#include <math.h>

#define NSP   589824   // 64*96*96
#define BATCH 2
#define TOPK  2048
#define CAND  4096
#define ANCH  12.0f

// ---------------- device scratch (no allocations allowed) ----------------
__device__ unsigned g_histA[BATCH][65536];
__device__ unsigned g_histB[BATCH][65536];
__device__ unsigned g_prefix[BATCH];
__device__ unsigned g_krem[BATCH];
__device__ unsigned g_thrlo[BATCH];   // low 16 bits of threshold key
__device__ unsigned g_dummy[BATCH];
__device__ unsigned g_cnt[BATCH];
__device__ unsigned long long g_cand[BATCH][CAND];
__device__ float    g_sc[BATCH][TOPK];
__device__ float    g_bx[BATCH][TOPK][6];
__device__ unsigned long long g_mask[BATCH][TOPK][32];

// ordered-uint key: larger key <=> larger float
__device__ __forceinline__ unsigned fkey(float f) {
    unsigned u = __float_as_uint(f);
    return (u & 0x80000000u) ? ~u : (u | 0x80000000u);
}
__device__ __forceinline__ float fromkey(unsigned k) {
    unsigned u = (k & 0x80000000u) ? (k ^ 0x80000000u) : ~k;
    return __uint_as_float(u);
}

// ---------------- K0: zero scratch (graph replays need re-zero) ----------
__global__ void k_zero() {
    int tid = blockIdx.x * blockDim.x + threadIdx.x;      // 512*256 = 131072
    ((unsigned*)g_histA)[tid] = 0u;
    ((unsigned*)g_histB)[tid] = 0u;
    if (tid < BATCH * CAND) ((unsigned long long*)g_cand)[tid] = 0ull;
    if (tid < BATCH) g_cnt[tid] = 0u;
}

// ---------------- K1: histogram of upper 16 key bits ---------------------
__global__ void k_hist1(const float* __restrict__ scores) {
    int b = blockIdx.y;
    int i = blockIdx.x * blockDim.x + threadIdx.x;
    if (i < NSP) {
        unsigned k = fkey(scores[b * NSP + i]);
        atomicAdd(&g_histA[b][k >> 16], 1u);
    }
}

// common: find bin p = max{x : count(bins>=x) >= K}; krem = K - count(bins>p)
__device__ void suffix_select(const unsigned* __restrict__ hist, unsigned K,
                              unsigned* outP, unsigned* outKrem) {
    __shared__ unsigned s[1024];
    int t = threadIdx.x;
    int base = t * 64;
    unsigned local = 0;
#pragma unroll 8
    for (int j = 0; j < 64; j++) local += hist[base + j];
    s[t] = local;
    __syncthreads();
    for (int off = 1; off < 1024; off <<= 1) {        // suffix-inclusive scan
        unsigned add = (t + off < 1024) ? s[t + off] : 0u;
        __syncthreads();
        s[t] += add;
        __syncthreads();
    }
    unsigned T = s[t] - local;                        // strictly above my bins
    if (T < K && T + local >= K) {                    // unique owner thread
        unsigned acc = T;
        for (int j = 63; j >= 0; j--) {
            unsigned h = hist[base + j];
            if (acc + h >= K) { *outP = (unsigned)(base + j); *outKrem = K - acc; break; }
            acc += h;
        }
    }
}

__global__ void k_sel1() {
    int b = blockIdx.x;
    suffix_select(g_histA[b], TOPK, &g_prefix[b], &g_krem[b]);
}

// ---------------- K3: histogram of lower 16 bits (matching prefix) -------
__global__ void k_hist2(const float* __restrict__ scores) {
    int b = blockIdx.y;
    int i = blockIdx.x * blockDim.x + threadIdx.x;
    if (i < NSP) {
        unsigned k = fkey(scores[b * NSP + i]);
        if ((k >> 16) == g_prefix[b]) atomicAdd(&g_histB[b][k & 0xFFFFu], 1u);
    }
}

__global__ void k_sel2() {
    int b = blockIdx.x;
    suffix_select(g_histB[b], g_krem[b], &g_thrlo[b], &g_dummy[b]);
}

// ---------------- K5: collect all elements with key >= threshold ---------
__global__ void k_collect(const float* __restrict__ scores) {
    int b = blockIdx.y;
    int i = blockIdx.x * blockDim.x + threadIdx.x;
    if (i < NSP) {
        unsigned thr = (g_prefix[b] << 16) | g_thrlo[b];
        unsigned k = fkey(scores[b * NSP + i]);
        if (k >= thr) {
            unsigned pos = atomicAdd(&g_cnt[b], 1u);
            if (pos < CAND)
                g_cand[b][pos] = ((unsigned long long)k << 32) | (unsigned)(~(unsigned)i);
        }
    }
}

// ---------------- K6: bitonic sort 4096 desc, gather + deparametrize -----
__global__ void k_sortgather(const float* __restrict__ bboxes) {
    int b = blockIdx.x, t = threadIdx.x;
    __shared__ unsigned long long s[CAND];
#pragma unroll
    for (int m = 0; m < 4; m++) s[m * 1024 + t] = g_cand[b][m * 1024 + t];
    __syncthreads();
    for (int k = 2; k <= CAND; k <<= 1) {
        for (int j = k >> 1; j > 0; j >>= 1) {
#pragma unroll
            for (int m = 0; m < 4; m++) {
                int i = m * 1024 + t;
                int l = i ^ j;
                if (l > i) {
                    unsigned long long a = s[i], c = s[l];
                    bool dsc = ((i & k) == 0);        // descending overall
                    if (dsc ? (a < c) : (a > c)) { s[i] = c; s[l] = a; }
                }
            }
            __syncthreads();
        }
    }
#pragma unroll
    for (int m = 0; m < 2; m++) {
        int i = m * 1024 + t;
        unsigned long long pk = s[i];
        unsigned key = (unsigned)(pk >> 32);
        unsigned idx = ~(unsigned)(pk & 0xFFFFFFFFull);
        g_sc[b][i] = fromkey(key);
        int z = idx / 9216, r = idx % 9216, y = r / 96, x = r % 96;
        long base = (long)b * 6 * NSP + idx;
        float czyx[3] = { (float)z + 0.5f, (float)y + 0.5f, (float)x + 0.5f };
#pragma unroll
        for (int c = 0; c < 3; c++)
            g_bx[b][i][c] = bboxes[base + (long)c * NSP] * ANCH + czyx[c];
#pragma unroll
        for (int c = 3; c < 6; c++)
            g_bx[b][i][c] = expf(bboxes[base + (long)c * NSP]) * ANCH;
    }
}

// ---------------- K7: 64x64-tile IoU bitmask ------------------------------
__global__ void k_iou() {
    int b = blockIdx.z, rb = blockIdx.y, cb = blockIdx.x, t = threadIdx.x;
    __shared__ float sc[64][7];                       // lo0..2, hi0..2, vol
    int col = cb * 64 + t;
    {
        float c0 = g_bx[b][col][0], c1 = g_bx[b][col][1], c2 = g_bx[b][col][2];
        float s0 = g_bx[b][col][3], s1 = g_bx[b][col][4], s2 = g_bx[b][col][5];
        sc[t][0] = c0 - 0.5f * s0; sc[t][1] = c1 - 0.5f * s1; sc[t][2] = c2 - 0.5f * s2;
        sc[t][3] = c0 + 0.5f * s0; sc[t][4] = c1 + 0.5f * s1; sc[t][5] = c2 + 0.5f * s2;
        sc[t][6] = s0 * s1 * s2;
    }
    __syncthreads();
    int row = rb * 64 + t;
    float r0 = g_bx[b][row][0], r1 = g_bx[b][row][1], r2 = g_bx[b][row][2];
    float s0 = g_bx[b][row][3], s1 = g_bx[b][row][4], s2 = g_bx[b][row][5];
    float rl0 = r0 - 0.5f * s0, rl1 = r1 - 0.5f * s1, rl2 = r2 - 0.5f * s2;
    float rh0 = r0 + 0.5f * s0, rh1 = r1 + 0.5f * s1, rh2 = r2 + 0.5f * s2;
    float rv = s0 * s1 * s2;
    unsigned long long bits = 0ull;
    if (cb * 64 + 63 > row) {
#pragma unroll 8
        for (int j = 0; j < 64; j++) {
            int cg = cb * 64 + j;
            if (cg > row) {
                float e0 = fmaxf(fminf(rh0, sc[j][3]) - fmaxf(rl0, sc[j][0]), 0.0f);
                float e1 = fmaxf(fminf(rh1, sc[j][4]) - fmaxf(rl1, sc[j][1]), 0.0f);
                float e2 = fmaxf(fminf(rh2, sc[j][5]) - fmaxf(rl2, sc[j][2]), 0.0f);
                float inter = e0 * e1 * e2;
                // iou > 0.25  <=>  inter > 0.25*(rv+cv-inter)  <=>  5*inter > rv+cv
                if (5.0f * inter > rv + sc[j][6]) bits |= (1ull << j);
            }
        }
    }
    g_mask[b][row][cb] = bits;
}

// ---------------- K8: sequential greedy NMS + output ----------------------
__global__ void k_nms(float* __restrict__ out) {
    int b = blockIdx.x, tid = threadIdx.x;
    __shared__ unsigned long long s_rows[2][32][32];
    __shared__ unsigned long long s_remv[32];
    unsigned long long remv = 0ull;

    // preload chunk 0 (32 rows x 32 words) with loader threads (tid >= 32)
    if (tid >= 32) {
        for (int k = tid - 32; k < 1024; k += 992) {
            int r = k >> 5, w = k & 31;
            s_rows[0][r][w] = g_mask[b][r][w];
        }
    }
    __syncthreads();

    for (int c = 0; c < 64; c++) {
        int cur = c & 1;
        if (tid >= 32 && c < 63) {                    // prefetch next chunk
            int nb = (c + 1) & 1;
            for (int k = tid - 32; k < 1024; k += 992) {
                int r = k >> 5, w = k & 31;
                s_rows[nb][r][w] = g_mask[b][((c + 1) << 5) + r][w];
            }
        }
        if (tid < 32) {                               // warp 0: sequential pass
#pragma unroll
            for (int rr = 0; rr < 32; rr++) {
                int i = (c << 5) + rr;
                unsigned long long rdat = s_rows[cur][rr][tid];
                unsigned long long wv = __shfl_sync(0xffffffffu, remv, i >> 6);
                if (!((wv >> (i & 63)) & 1ull)) remv |= rdat;
            }
        }
        __syncthreads();
    }
    if (tid < 32) s_remv[tid] = remv;
    __syncthreads();

#pragma unroll
    for (int m = 0; m < 2; m++) {
        int i = m * 1024 + tid;
        bool keep = !((s_remv[i >> 6] >> (i & 63)) & 1ull);
        float* o = out + ((long)b * TOPK + i) * 7;
        o[0] = keep ? g_sc[b][i] : 0.0f;
#pragma unroll
        for (int c = 0; c < 6; c++) o[1 + c] = keep ? g_bx[b][i][c] : 0.0f;
    }
}

// ---------------- launch --------------------------------------------------
extern "C" void kernel_launch(void* const* d_in, const int* in_sizes, int n_in,
                              void* d_out, int out_size) {
    const float* bboxes = (const float*)d_in[0];   // (2,6,64,96,96)
    const float* scores = (const float*)d_in[1];   // (2,64,96,96)
    float* out = (float*)d_out;                    // (2,2048,7)

    dim3 gsc((NSP + 255) / 256, BATCH);
    k_zero<<<512, 256>>>();
    k_hist1<<<gsc, 256>>>(scores);
    k_sel1<<<BATCH, 1024>>>();
    k_hist2<<<gsc, 256>>>(scores);
    k_sel2<<<BATCH, 1024>>>();
    k_collect<<<gsc, 256>>>(scores);
    k_sortgather<<<BATCH, 1024>>>(bboxes);
    k_iou<<<dim3(32, 32, BATCH), 64>>>();
    k_nms<<<BATCH, 1024>>>(out);
}

// round 3
// speedup vs baseline: 1.3311x; 1.3311x over previous
#include <cuda_runtime.h>
#include <math.h>

#define NSP   589824   // 64*96*96
#define BATCH 2
#define TOPK  2048
#define CAND  4096
#define STASH 16384
#define ANCH  12.0f

// ---------------- device scratch (no allocations allowed) ----------------
__device__ __align__(16) unsigned g_histA[BATCH][65536];
__device__ __align__(16) unsigned g_histB[BATCH][65536];
__device__ unsigned g_prefix[BATCH];
__device__ unsigned g_krem[BATCH];
__device__ unsigned g_thrlo[BATCH];
__device__ unsigned g_dummy[BATCH];
__device__ unsigned g_cnt[BATCH];
__device__ unsigned g_scnt[BATCH];
__device__ __align__(16) unsigned long long g_cand[BATCH][CAND];
__device__ __align__(16) unsigned long long g_stash[BATCH][STASH];
__device__ float    g_sc[BATCH][TOPK];
__device__ float    g_bx[BATCH][TOPK][6];
__device__ __align__(16) float g_pb[BATCH][TOPK][8];  // lo0,lo1,lo2,hi0 | hi1,hi2,vol,0
__device__ __align__(16) unsigned long long g_mask[BATCH][TOPK][32];

__device__ __forceinline__ unsigned fkey(float f) {
    unsigned u = __float_as_uint(f);
    return (u & 0x80000000u) ? ~u : (u | 0x80000000u);
}
__device__ __forceinline__ float fromkey(unsigned k) {
    unsigned u = (k & 0x80000000u) ? (k ^ 0x80000000u) : ~k;
    return __uint_as_float(u);
}

// ---------------- K0: zero scratch -----------------------------------------
// u64 slots: histA 65536, histB 65536, mask 131072, cand 8192 -> 270336 total
__global__ void k_zero() {
    unsigned i = blockIdx.x * blockDim.x + threadIdx.x;   // 1056*256 = 270336
    if (i < 65536)       ((unsigned long long*)g_histA)[i] = 0ull;
    else if (i < 131072) ((unsigned long long*)g_histB)[i - 65536] = 0ull;
    else if (i < 262144) ((unsigned long long*)g_mask)[i - 131072] = 0ull;
    else                 ((unsigned long long*)g_cand)[i - 262144] = 0ull;
    if (i < BATCH) { g_cnt[i] = 0u; g_scnt[i] = 0u; }
}

// ---------------- K1: histogram of upper 16 key bits (float4) --------------
__global__ void k_hist1(const float* __restrict__ scores) {
    int b = blockIdx.y;
    int i = blockIdx.x * blockDim.x + threadIdx.x;        // NSP/4 threads
    float4 v = ((const float4*)(scores + (long)b * NSP))[i];
    atomicAdd(&g_histA[b][fkey(v.x) >> 16], 1u);
    atomicAdd(&g_histA[b][fkey(v.y) >> 16], 1u);
    atomicAdd(&g_histA[b][fkey(v.z) >> 16], 1u);
    atomicAdd(&g_histA[b][fkey(v.w) >> 16], 1u);
}

// find bin p = max{x : count(bins>=x) >= K}; krem = K - count(bins>p)
__device__ void suffix_select(const unsigned* __restrict__ hist, unsigned K,
                              unsigned* outP, unsigned* outKrem) {
    __shared__ unsigned s[1024];
    int t = threadIdx.x;
    const uint4* h4 = (const uint4*)hist + t * 16;
    unsigned local = 0;
#pragma unroll
    for (int j = 0; j < 16; j++) {
        uint4 v = h4[j];
        local += v.x + v.y + v.z + v.w;
    }
    s[t] = local;
    __syncthreads();
    for (int off = 1; off < 1024; off <<= 1) {
        unsigned add = (t + off < 1024) ? s[t + off] : 0u;
        __syncthreads();
        s[t] += add;
        __syncthreads();
    }
    unsigned T = s[t] - local;
    if (T < K && T + local >= K) {
        unsigned acc = T, P = 0, KR = 0;
        int found = 0;
        for (int j = 15; j >= 0; j--) {
            uint4 v = h4[j];
            unsigned hv[4] = { v.w, v.z, v.y, v.x };
#pragma unroll
            for (int q = 0; q < 4; q++) {
                if (!found) {
                    if (acc + hv[q] >= K) { P = (unsigned)(t*64 + 4*j + (3-q)); KR = K - acc; found = 1; }
                    else acc += hv[q];
                }
            }
        }
        *outP = P; *outKrem = KR;
    }
}

__global__ void __launch_bounds__(1024) k_sel1() {
    int b = blockIdx.x; suffix_select(g_histA[b], TOPK, &g_prefix[b], &g_krem[b]);
}

// ---------------- K3: fused low-bit histogram + direct collect -------------
__global__ void k_pass2(const float* __restrict__ scores) {
    int b = blockIdx.y;
    int i = blockIdx.x * blockDim.x + threadIdx.x;        // NSP/4 threads
    unsigned pref = g_prefix[b];
    float4 v = ((const float4*)(scores + (long)b * NSP))[i];
    float vv[4] = { v.x, v.y, v.z, v.w };
#pragma unroll
    for (int q = 0; q < 4; q++) {
        unsigned k = fkey(vv[q]);
        unsigned p = k >> 16;
        if (p >= pref) {
            unsigned idx = (unsigned)(i * 4 + q);
            unsigned long long pk = ((unsigned long long)k << 32) | (unsigned)(~idx);
            if (p > pref) {
                unsigned pos = atomicAdd(&g_cnt[b], 1u);
                if (pos < CAND) g_cand[b][pos] = pk;
            } else {
                atomicAdd(&g_histB[b][k & 0xFFFFu], 1u);
                unsigned sq = atomicAdd(&g_scnt[b], 1u);
                if (sq < STASH) g_stash[b][sq] = pk;
            }
        }
    }
}

__global__ void __launch_bounds__(1024) k_sel2() {
    int b = blockIdx.x; suffix_select(g_histB[b], g_krem[b], &g_thrlo[b], &g_dummy[b]);
}

// ---------------- K5: finish collecting from the stash ---------------------
__global__ void k_finish() {
    int b = blockIdx.x;
    unsigned n = g_scnt[b]; if (n > STASH) n = STASH;
    unsigned thr = g_thrlo[b];
    for (unsigned q = threadIdx.x; q < n; q += 256) {
        unsigned long long pk = g_stash[b][q];
        if (((unsigned)(pk >> 32) & 0xFFFFu) >= thr) {
            unsigned pos = atomicAdd(&g_cnt[b], 1u);
            if (pos < CAND) g_cand[b][pos] = pk;
        }
    }
}

// ---------------- K6: bitonic sort 4096 desc, gather + deparametrize -------
__global__ void __launch_bounds__(1024) k_sortgather(const float* __restrict__ bboxes) {
    int b = blockIdx.x, t = threadIdx.x;
    __shared__ unsigned long long s[CAND];
#pragma unroll
    for (int m = 0; m < 4; m++) s[m * 1024 + t] = g_cand[b][m * 1024 + t];
    __syncthreads();
    for (int k = 2; k <= CAND; k <<= 1) {
        for (int j = k >> 1; j > 0; j >>= 1) {
#pragma unroll
            for (int m = 0; m < 4; m++) {
                int i = m * 1024 + t;
                int l = i ^ j;
                if (l > i) {
                    unsigned long long a = s[i], c = s[l];
                    bool dsc = ((i & k) == 0);
                    if (dsc ? (a < c) : (a > c)) { s[i] = c; s[l] = a; }
                }
            }
            __syncthreads();
        }
    }
#pragma unroll
    for (int m = 0; m < 2; m++) {
        int i = m * 1024 + t;
        unsigned long long pk = s[i];
        unsigned key = (unsigned)(pk >> 32);
        unsigned idx = ~(unsigned)(pk & 0xFFFFFFFFull);
        g_sc[b][i] = fromkey(key);
        int z = idx / 9216, r = idx % 9216, y = r / 96, x = r % 96;
        long base = (long)b * 6 * NSP + idx;
        float czyx[3] = { (float)z + 0.5f, (float)y + 0.5f, (float)x + 0.5f };
        float c3[3], s3[3];
#pragma unroll
        for (int c = 0; c < 3; c++) {
            c3[c] = bboxes[base + (long)c * NSP] * ANCH + czyx[c];
            g_bx[b][i][c] = c3[c];
        }
#pragma unroll
        for (int c = 0; c < 3; c++) {
            s3[c] = expf(bboxes[base + (long)(c + 3) * NSP]) * ANCH;
            g_bx[b][i][c + 3] = s3[c];
        }
        float4 L = make_float4(c3[0] - 0.5f * s3[0], c3[1] - 0.5f * s3[1],
                               c3[2] - 0.5f * s3[2], c3[0] + 0.5f * s3[0]);
        float4 H = make_float4(c3[1] + 0.5f * s3[1], c3[2] + 0.5f * s3[2],
                               s3[0] * s3[1] * s3[2], 0.0f);
        ((float4*)g_pb[b][i])[0] = L;
        ((float4*)g_pb[b][i])[1] = H;
    }
}

// ---------------- K7: IoU bitmask, 256 rows x 64 cols per block ------------
__global__ void __launch_bounds__(128) k_iou() {
    int b = blockIdx.z, rbk = blockIdx.y, cb = blockIdx.x, t = threadIdx.x;
    int row0 = rbk << 8;
    int c0 = cb << 6;
    if (c0 + 63 <= row0) return;                       // tile entirely below diag
    __shared__ float4 scol[64][2];
    { int j = t >> 1, h = t & 1; scol[j][h] = ((const float4*)g_pb[b][c0 + j])[h]; }
    __syncthreads();
    int r1 = row0 + t, r2 = row0 + 128 + t;
    float4 aL = ((const float4*)g_pb[b][r1])[0];
    float4 aH = ((const float4*)g_pb[b][r1])[1];
    float4 bL = ((const float4*)g_pb[b][r2])[0];
    float4 bH = ((const float4*)g_pb[b][r2])[1];
    unsigned long long bits1 = 0ull, bits2 = 0ull;
#pragma unroll
    for (int j = 0; j < 64; j++) {
        float4 cL = scol[j][0], cH = scol[j][1];
        {
            float e0 = fmaxf(fminf(aL.w, cL.w) - fmaxf(aL.x, cL.x), 0.0f);
            float e1 = fmaxf(fminf(aH.x, cH.x) - fmaxf(aL.y, cL.y), 0.0f);
            float e2 = fmaxf(fminf(aH.y, cH.y) - fmaxf(aL.z, cL.z), 0.0f);
            float inter = e0 * e1 * e2;
            if (5.0f * inter > aH.z + cH.z) bits1 |= (1ull << j);
        }
        {
            float e0 = fmaxf(fminf(bL.w, cL.w) - fmaxf(bL.x, cL.x), 0.0f);
            float e1 = fmaxf(fminf(bH.x, cH.x) - fmaxf(bL.y, cL.y), 0.0f);
            float e2 = fmaxf(fminf(bH.y, cH.y) - fmaxf(bL.z, cL.z), 0.0f);
            float inter = e0 * e1 * e2;
            if (5.0f * inter > bH.z + cH.z) bits2 |= (1ull << j);
        }
    }
    if (c0 + 63 > r1) {
        if (r1 >= c0) { int k = r1 - c0; bits1 &= (~0ull) << (k + 1); }
        g_mask[b][r1][cb] = bits1;
    }
    if (c0 + 63 > r2) {
        if (r2 >= c0) { int k = r2 - c0; bits2 &= (~0ull) << (k + 1); }
        g_mask[b][r2][cb] = bits2;
    }
}

// ---------------- K8: sequential greedy NMS (short chain) + output ---------
__global__ void __launch_bounds__(1024) k_nms(float* __restrict__ out) {
    int b = blockIdx.x, tid = threadIdx.x;
    __shared__ unsigned long long s_rows[2][64][32];
    __shared__ unsigned long long s_remv[32];
    unsigned long long remv = 0ull;

    if (tid >= 32) {                                   // preload chunk 0 (64 rows)
        for (int k = tid - 32; k < 2048; k += 992) {
            s_rows[0][k >> 5][k & 31] = g_mask[b][k >> 5][k & 31];
        }
    }
    __syncthreads();

    for (int c = 0; c < 32; c++) {                     // 32 chunks of 64 rows
        int cur = c & 1;
        if (tid >= 32 && c < 31) {
            int nb = cur ^ 1;
            for (int k = tid - 32; k < 2048; k += 992) {
                s_rows[nb][k >> 5][k & 31] = g_mask[b][((c + 1) << 6) + (k >> 5)][k & 31];
            }
        }
        if (tid < 32) {
            unsigned long long local = __shfl_sync(0xffffffffu, remv, c);
#pragma unroll
            for (int rr = 0; rr < 64; rr++) {
                unsigned long long rdat = s_rows[cur][rr][tid];
                unsigned long long wv = __shfl_sync(0xffffffffu, rdat, c);  // off-chain
                unsigned long long m =
                    (unsigned long long)((long long)(local << (63 - rr)) >> 63);
                remv |= rdat & ~m;
                local |= wv & ~m;
            }
        }
        __syncthreads();
    }
    if (tid < 32) s_remv[tid] = remv;
    __syncthreads();

#pragma unroll
    for (int m = 0; m < 2; m++) {
        int i = m * 1024 + tid;
        bool keep = !((s_remv[i >> 6] >> (i & 63)) & 1ull);
        float* o = out + ((long)b * TOPK + i) * 7;
        o[0] = keep ? g_sc[b][i] : 0.0f;
#pragma unroll
        for (int c = 0; c < 6; c++) o[1 + c] = keep ? g_bx[b][i][c] : 0.0f;
    }
}

// ---------------- launch ---------------------------------------------------
extern "C" void kernel_launch(void* const* d_in, const int* in_sizes, int n_in,
                              void* d_out, int out_size) {
    const float* bboxes = (const float*)d_in[0];   // (2,6,64,96,96)
    const float* scores = (const float*)d_in[1];   // (2,64,96,96)
    float* out = (float*)d_out;                    // (2,2048,7)

    dim3 g4((NSP / 4 + 255) / 256, BATCH);         // 576 x 2
    k_zero<<<1056, 256>>>();
    k_hist1<<<g4, 256>>>(scores);
    k_sel1<<<BATCH, 1024>>>();
    k_pass2<<<g4, 256>>>(scores);
    k_sel2<<<BATCH, 1024>>>();
    k_finish<<<BATCH, 256>>>();
    k_sortgather<<<BATCH, 1024>>>(bboxes);
    k_iou<<<dim3(32, 8, BATCH), 128>>>();
    k_nms<<<BATCH, 1024>>>(out);
}

// round 4
// speedup vs baseline: 1.6196x; 1.2167x over previous
#include <cuda_runtime.h>
#include <math.h>

#define NSP   589824   // 64*96*96
#define BATCH 2
#define TOPK  2048
#define CAND  4096
#define STASH 16384
#define ANCH  12.0f
#define Q4    36864    // NSP/16 : float4 slots per pass chunk

// ---------------- device scratch (zero-initialized at load; re-zeroed each
// replay by k_iou's cleanup tail so the graph is replay-stable) -------------
__device__ __align__(16) unsigned g_histA[BATCH][65536];
__device__ __align__(16) unsigned g_histB[BATCH][65536];
__device__ unsigned g_prefix[BATCH];
__device__ unsigned g_krem[BATCH];
__device__ unsigned g_cnt[BATCH];
__device__ unsigned g_scnt[BATCH];
__device__ __align__(16) unsigned long long g_cand[BATCH][CAND];
__device__ __align__(16) unsigned long long g_stash[BATCH][STASH];
__device__ float    g_sc[BATCH][TOPK];
__device__ unsigned g_sidx[BATCH][TOPK];
__device__ float    g_bx[BATCH][TOPK][6];
__device__ __align__(16) float g_pb[BATCH][TOPK][8];  // lo0,lo1,lo2,hi0 | hi1,hi2,vol,0
__device__ __align__(16) unsigned long long g_mask[BATCH][TOPK][32]; // never zeroed; junk masked in k_nms

__device__ __forceinline__ unsigned fkey(float f) {
    unsigned u = __float_as_uint(f);
    return (u & 0x80000000u) ? ~u : (u | 0x80000000u);
}
__device__ __forceinline__ float fromkey(unsigned k) {
    unsigned u = (k & 0x80000000u) ? (k ^ 0x80000000u) : ~k;
    return __uint_as_float(u);
}

// ---------------- K1: histogram of upper 16 key bits (MLP=4) ---------------
__global__ void k_hist1(const float* __restrict__ scores) {
    int b = blockIdx.y;
    int t = blockIdx.x * blockDim.x + threadIdx.x;        // 0..Q4-1
    const float4* p = (const float4*)(scores + (long)b * NSP);
    float4 v0 = p[t], v1 = p[t + Q4], v2 = p[t + 2 * Q4], v3 = p[t + 3 * Q4];
    float vv[16] = { v0.x,v0.y,v0.z,v0.w, v1.x,v1.y,v1.z,v1.w,
                     v2.x,v2.y,v2.z,v2.w, v3.x,v3.y,v3.z,v3.w };
#pragma unroll
    for (int q = 0; q < 16; q++) atomicAdd(&g_histA[b][fkey(vv[q]) >> 16], 1u);
}

// find bin p = max{x : count(bins>=x) >= K}; krem = K - count(bins>p)
__device__ void suffix_select(const unsigned* __restrict__ hist, unsigned K,
                              unsigned* outP, unsigned* outKrem) {
    __shared__ unsigned s[1024];
    int t = threadIdx.x;
    const uint4* h4 = (const uint4*)hist + t * 16;
    unsigned local = 0;
#pragma unroll
    for (int j = 0; j < 16; j++) {
        uint4 v = h4[j];
        local += v.x + v.y + v.z + v.w;
    }
    s[t] = local;
    __syncthreads();
    for (int off = 1; off < 1024; off <<= 1) {
        unsigned add = (t + off < 1024) ? s[t + off] : 0u;
        __syncthreads();
        s[t] += add;
        __syncthreads();
    }
    unsigned T = s[t] - local;
    if (T < K && T + local >= K) {
        unsigned acc = T, P = 0, KR = 0;
        int found = 0;
        for (int j = 15; j >= 0; j--) {
            uint4 v = h4[j];
            unsigned hv[4] = { v.w, v.z, v.y, v.x };
#pragma unroll
            for (int q = 0; q < 4; q++) {
                if (!found) {
                    if (acc + hv[q] >= K) { P = (unsigned)(t*64 + 4*j + (3-q)); KR = K - acc; found = 1; }
                    else acc += hv[q];
                }
            }
        }
        *outP = P; *outKrem = KR;
    }
}

__global__ void __launch_bounds__(1024) k_sel1() {
    int b = blockIdx.x; suffix_select(g_histA[b], TOPK, &g_prefix[b], &g_krem[b]);
}

// ---------------- K3: low-bit histogram + collect (MLP=4) ------------------
__global__ void k_pass2(const float* __restrict__ scores) {
    int b = blockIdx.y;
    int t = blockIdx.x * blockDim.x + threadIdx.x;        // 0..Q4-1
    unsigned pref = g_prefix[b];
    const float4* p = (const float4*)(scores + (long)b * NSP);
    float4 v[4] = { p[t], p[t + Q4], p[t + 2 * Q4], p[t + 3 * Q4] };
#pragma unroll
    for (int kk = 0; kk < 4; kk++) {
        float vv[4] = { v[kk].x, v[kk].y, v[kk].z, v[kk].w };
#pragma unroll
        for (int q = 0; q < 4; q++) {
            unsigned k = fkey(vv[q]);
            unsigned pp = k >> 16;
            if (pp >= pref) {
                unsigned idx = (unsigned)((t + kk * Q4) * 4 + q);
                unsigned long long pk = ((unsigned long long)k << 32) | (unsigned)(~idx);
                if (pp > pref) {
                    unsigned pos = atomicAdd(&g_cnt[b], 1u);
                    if (pos < CAND) g_cand[b][pos] = pk;
                } else {
                    atomicAdd(&g_histB[b][k & 0xFFFFu], 1u);
                    unsigned sq = atomicAdd(&g_scnt[b], 1u);
                    if (sq < STASH) g_stash[b][sq] = pk;
                }
            }
        }
    }
}

// ---------------- K4: select low bits + finish collect + bitonic sort ------
__global__ void __launch_bounds__(1024) k_selsort() {
    int b = blockIdx.x, t = threadIdx.x;
    __shared__ unsigned sh_thr, sh_d;
    __shared__ unsigned long long s[CAND];
    suffix_select(g_histB[b], g_krem[b], &sh_thr, &sh_d);
    __syncthreads();
    unsigned thr = sh_thr;
    unsigned n = g_scnt[b]; if (n > STASH) n = STASH;
    for (unsigned q = t; q < n; q += 1024) {
        unsigned long long pk = g_stash[b][q];
        if (((unsigned)(pk >> 32) & 0xFFFFu) >= thr) {
            unsigned pos = atomicAdd(&g_cnt[b], 1u);
            if (pos < CAND) g_cand[b][pos] = pk;
        }
    }
    __syncthreads();                                   // block-wide fence
#pragma unroll
    for (int m = 0; m < 4; m++) s[m * 1024 + t] = g_cand[b][m * 1024 + t];
    __syncthreads();
    for (int k = 2; k <= CAND; k <<= 1) {
        for (int j = k >> 1; j > 0; j >>= 1) {
#pragma unroll
            for (int m = 0; m < 4; m++) {
                int i = m * 1024 + t;
                int l = i ^ j;
                if (l > i) {
                    unsigned long long a = s[i], c = s[l];
                    bool dsc = ((i & k) == 0);
                    if (dsc ? (a < c) : (a > c)) { s[i] = c; s[l] = a; }
                }
            }
            __syncthreads();
        }
    }
#pragma unroll
    for (int m = 0; m < 2; m++) {
        int i = m * 1024 + t;
        unsigned long long pk = s[i];
        g_sc[b][i]   = fromkey((unsigned)(pk >> 32));
        g_sidx[b][i] = ~(unsigned)(pk & 0xFFFFFFFFull);
    }
}

// ---------------- K5: wide gather + deparametrize --------------------------
__global__ void k_gather(const float* __restrict__ bboxes) {
    int gi = blockIdx.x * 128 + threadIdx.x;           // 0..4095
    int b = gi >> 11, i = gi & (TOPK - 1);
    unsigned idx = g_sidx[b][i];
    int z = idx / 9216, r = idx % 9216, y = r / 96, x = r % 96;
    long base = (long)b * 6 * NSP + idx;
    float czyx[3] = { (float)z + 0.5f, (float)y + 0.5f, (float)x + 0.5f };
    float c3[3], s3[3];
#pragma unroll
    for (int c = 0; c < 3; c++) {
        c3[c] = bboxes[base + (long)c * NSP] * ANCH + czyx[c];
        g_bx[b][i][c] = c3[c];
    }
#pragma unroll
    for (int c = 0; c < 3; c++) {
        s3[c] = expf(bboxes[base + (long)(c + 3) * NSP]) * ANCH;
        g_bx[b][i][c + 3] = s3[c];
    }
    float4 L = make_float4(c3[0] - 0.5f * s3[0], c3[1] - 0.5f * s3[1],
                           c3[2] - 0.5f * s3[2], c3[0] + 0.5f * s3[0]);
    float4 H = make_float4(c3[1] + 0.5f * s3[1], c3[2] + 0.5f * s3[2],
                           s3[0] * s3[1] * s3[2], 0.0f);
    ((float4*)g_pb[b][i])[0] = L;
    ((float4*)g_pb[b][i])[1] = H;
}

// ---------------- K6: IoU bitmask + replay-state cleanup -------------------
__global__ void __launch_bounds__(128) k_iou() {
    int b = blockIdx.z, rbk = blockIdx.y, cb = blockIdx.x, t = threadIdx.x;
    // cleanup tail for next graph replay: zero hists + cand + counters
    {
        unsigned flat = ((blockIdx.z * gridDim.y + blockIdx.y) * gridDim.x + blockIdx.x) * 128u + t;
        for (unsigned u = flat; u < 139264u; u += 65536u) {     // u64 slots
            if (u < 65536u)       ((unsigned long long*)g_histA)[u] = 0ull;
            else if (u < 131072u) ((unsigned long long*)g_histB)[u - 65536u] = 0ull;
            else                  ((unsigned long long*)g_cand)[u - 131072u] = 0ull;
        }
        if (flat < BATCH) { g_cnt[flat] = 0u; g_scnt[flat] = 0u; }
    }
    int row0 = rbk << 8;
    int c0 = cb << 6;
    if (c0 + 63 <= row0) return;                       // tile entirely below diag
    __shared__ float4 scol[64][2];
    { int j = t >> 1, h = t & 1; scol[j][h] = ((const float4*)g_pb[b][c0 + j])[h]; }
    __syncthreads();
    int r1 = row0 + t, r2 = row0 + 128 + t;
    float4 aL = ((const float4*)g_pb[b][r1])[0];
    float4 aH = ((const float4*)g_pb[b][r1])[1];
    float4 bL = ((const float4*)g_pb[b][r2])[0];
    float4 bH = ((const float4*)g_pb[b][r2])[1];
    unsigned a0 = 0u, a1 = 0u, b0 = 0u, b1 = 0u;
#pragma unroll
    for (int j = 0; j < 64; j++) {
        float4 cL = scol[j][0], cH = scol[j][1];
        float e0 = fmaxf(fminf(aL.w, cL.w) - fmaxf(aL.x, cL.x), 0.0f);
        float e1 = fmaxf(fminf(aH.x, cH.x) - fmaxf(aL.y, cL.y), 0.0f);
        float e2 = fmaxf(fminf(aH.y, cH.y) - fmaxf(aL.z, cL.z), 0.0f);
        float inter1 = e0 * e1 * e2;
        bool p1 = (5.0f * inter1 > aH.z + cH.z);
        float f0 = fmaxf(fminf(bL.w, cL.w) - fmaxf(bL.x, cL.x), 0.0f);
        float f1 = fmaxf(fminf(bH.x, cH.x) - fmaxf(bL.y, cL.y), 0.0f);
        float f2 = fmaxf(fminf(bH.y, cH.y) - fmaxf(bL.z, cL.z), 0.0f);
        float inter2 = f0 * f1 * f2;
        bool p2 = (5.0f * inter2 > bH.z + cH.z);
        unsigned bb = 1u << (j & 31);
        if (j < 32) { if (p1) a0 |= bb; if (p2) b0 |= bb; }
        else        { if (p1) a1 |= bb; if (p2) b1 |= bb; }
    }
    unsigned long long bits1 = (unsigned long long)a0 | ((unsigned long long)a1 << 32);
    unsigned long long bits2 = (unsigned long long)b0 | ((unsigned long long)b1 << 32);
    if (c0 + 63 > r1) {
        if (r1 >= c0) { int k = r1 - c0; bits1 &= (~0ull) << (k + 1); }
        g_mask[b][r1][cb] = bits1;
    }
    if (c0 + 63 > r2) {
        if (r2 >= c0) { int k = r2 - c0; bits2 &= (~0ull) << (k + 1); }
        g_mask[b][r2][cb] = bits2;
    }
}

// ---------------- K7: sequential greedy NMS (LDS-broadcast chain) ----------
__global__ void __launch_bounds__(1024) k_nms(float* __restrict__ out) {
    int b = blockIdx.x, tid = threadIdx.x;
    __shared__ unsigned long long s_rows[2][64][32];
    __shared__ unsigned long long s_remv[32];
    unsigned long long remv = 0ull;

    if (tid >= 32) {                                   // preload chunk 0 (64 rows)
        for (int k = tid - 32; k < 2048; k += 992) {
            s_rows[0][k >> 5][k & 31] = g_mask[b][k >> 5][k & 31];
        }
    }
    __syncthreads();

    for (int c = 0; c < 32; c++) {                     // 32 chunks of 64 rows
        int cur = c & 1;
        if (tid >= 32 && c < 31) {
            int nb = cur ^ 1;
            for (int k = tid - 32; k < 2048; k += 992) {
                s_rows[nb][k >> 5][k & 31] = g_mask[b][((c + 1) << 6) + (k >> 5)][k & 31];
            }
        }
        if (tid < 32) {
            unsigned long long local = __shfl_sync(0xffffffffu, remv, c);
#pragma unroll
            for (int rr = 0; rr < 64; rr++) {
                int i = (c << 6) + rr;
                unsigned long long rdat = s_rows[cur][rr][tid];
                unsigned long long rloc = s_rows[cur][rr][c];   // broadcast LDS, off-chain
                if (64 * tid + 63 <= i) rdat = 0ull;            // mask unwritten words
                unsigned long long m =
                    (unsigned long long)((long long)(local << (63 - rr)) >> 63);
                remv |= rdat & ~m;
                local |= rloc & ~m;
            }
        }
        __syncthreads();
    }
    if (tid < 32) s_remv[tid] = remv;
    __syncthreads();

#pragma unroll
    for (int m = 0; m < 2; m++) {
        int i = m * 1024 + tid;
        bool keep = !((s_remv[i >> 6] >> (i & 63)) & 1ull);
        float* o = out + ((long)b * TOPK + i) * 7;
        o[0] = keep ? g_sc[b][i] : 0.0f;
#pragma unroll
        for (int c = 0; c < 6; c++) o[1 + c] = keep ? g_bx[b][i][c] : 0.0f;
    }
}

// ---------------- launch ---------------------------------------------------
extern "C" void kernel_launch(void* const* d_in, const int* in_sizes, int n_in,
                              void* d_out, int out_size) {
    const float* bboxes = (const float*)d_in[0];   // (2,6,64,96,96)
    const float* scores = (const float*)d_in[1];   // (2,64,96,96)
    float* out = (float*)d_out;                    // (2,2048,7)

    dim3 g16(Q4 / 256, BATCH);                     // 144 x 2
    k_hist1<<<g16, 256>>>(scores);
    k_sel1<<<BATCH, 1024>>>();
    k_pass2<<<g16, 256>>>(scores);
    k_selsort<<<BATCH, 1024>>>();
    k_gather<<<32, 128>>>(bboxes);
    k_iou<<<dim3(32, 8, BATCH), 128>>>();
    k_nms<<<BATCH, 1024>>>(out);
}

// round 5
// speedup vs baseline: 1.7711x; 1.0935x over previous
#include <cuda_runtime.h>
#include <math.h>

#define NSP   589824   // 64*96*96
#define BATCH 2
#define TOPK  2048
#define CAND  4096
#define STASH 16384
#define ANCH  12.0f
#define Q4    36864    // NSP/16 : float4 slots per pass chunk

// ---------------- device scratch (zero-initialized at load; re-zeroed each
// replay by k_iou's cleanup tail so the graph is replay-stable) -------------
__device__ __align__(16) unsigned g_histA[BATCH][65536];
__device__ __align__(16) unsigned g_histB[BATCH][65536];
__device__ unsigned g_prefix[BATCH];
__device__ unsigned g_krem[BATCH];
__device__ unsigned g_cnt[BATCH];
__device__ unsigned g_scnt[BATCH];
__device__ __align__(16) unsigned long long g_cand[BATCH][CAND];
__device__ __align__(16) unsigned long long g_stash[BATCH][STASH];
__device__ float    g_sc[BATCH][TOPK];
__device__ float    g_bx[BATCH][TOPK][6];
__device__ __align__(16) float g_pb[BATCH][TOPK][8];  // lo0,lo1,lo2,hi0 | hi1,hi2,vol,0
__device__ __align__(16) unsigned long long g_mask[BATCH][TOPK][32]; // junk masked in k_nms

__device__ __forceinline__ unsigned fkey(float f) {
    unsigned u = __float_as_uint(f);
    return (u & 0x80000000u) ? ~u : (u | 0x80000000u);
}
__device__ __forceinline__ float fromkey(unsigned k) {
    unsigned u = (k & 0x80000000u) ? (k ^ 0x80000000u) : ~k;
    return __uint_as_float(u);
}

// ---------------- K1: histogram of upper 16 key bits (MLP=4) ---------------
__global__ void k_hist1(const float* __restrict__ scores) {
    int b = blockIdx.y;
    int t = blockIdx.x * blockDim.x + threadIdx.x;        // 0..Q4-1
    const float4* p = (const float4*)(scores + (long)b * NSP);
    float4 v0 = p[t], v1 = p[t + Q4], v2 = p[t + 2 * Q4], v3 = p[t + 3 * Q4];
    float vv[16] = { v0.x,v0.y,v0.z,v0.w, v1.x,v1.y,v1.z,v1.w,
                     v2.x,v2.y,v2.z,v2.w, v3.x,v3.y,v3.z,v3.w };
#pragma unroll
    for (int q = 0; q < 16; q++) atomicAdd(&g_histA[b][fkey(vv[q]) >> 16], 1u);
}

// find bin p = max{x : count(bins>=x) >= K}; krem = K - count(bins>p)
__device__ void suffix_select(const unsigned* __restrict__ hist, unsigned K,
                              unsigned* outP, unsigned* outKrem) {
    __shared__ unsigned s[1024];
    int t = threadIdx.x;
    const uint4* h4 = (const uint4*)hist + t * 16;
    unsigned local = 0;
#pragma unroll
    for (int j = 0; j < 16; j++) {
        uint4 v = h4[j];
        local += v.x + v.y + v.z + v.w;
    }
    s[t] = local;
    __syncthreads();
    for (int off = 1; off < 1024; off <<= 1) {
        unsigned add = (t + off < 1024) ? s[t + off] : 0u;
        __syncthreads();
        s[t] += add;
        __syncthreads();
    }
    unsigned T = s[t] - local;
    if (T < K && T + local >= K) {
        unsigned acc = T, P = 0, KR = 0;
        int found = 0;
        for (int j = 15; j >= 0; j--) {
            uint4 v = h4[j];
            unsigned hv[4] = { v.w, v.z, v.y, v.x };
#pragma unroll
            for (int q = 0; q < 4; q++) {
                if (!found) {
                    if (acc + hv[q] >= K) { P = (unsigned)(t*64 + 4*j + (3-q)); KR = K - acc; found = 1; }
                    else acc += hv[q];
                }
            }
        }
        *outP = P; *outKrem = KR;
    }
}

__global__ void __launch_bounds__(1024) k_sel1() {
    int b = blockIdx.x; suffix_select(g_histA[b], TOPK, &g_prefix[b], &g_krem[b]);
}

// ---------------- K3: low-bit histogram + collect (MLP=4) ------------------
__global__ void k_pass2(const float* __restrict__ scores) {
    int b = blockIdx.y;
    int t = blockIdx.x * blockDim.x + threadIdx.x;        // 0..Q4-1
    unsigned pref = g_prefix[b];
    const float4* p = (const float4*)(scores + (long)b * NSP);
    float4 v[4] = { p[t], p[t + Q4], p[t + 2 * Q4], p[t + 3 * Q4] };
#pragma unroll
    for (int kk = 0; kk < 4; kk++) {
        float vv[4] = { v[kk].x, v[kk].y, v[kk].z, v[kk].w };
#pragma unroll
        for (int q = 0; q < 4; q++) {
            unsigned k = fkey(vv[q]);
            unsigned pp = k >> 16;
            if (pp >= pref) {
                unsigned idx = (unsigned)((t + kk * Q4) * 4 + q);
                unsigned long long pk = ((unsigned long long)k << 32) | (unsigned)(~idx);
                if (pp > pref) {
                    unsigned pos = atomicAdd(&g_cnt[b], 1u);
                    if (pos < CAND) g_cand[b][pos] = pk;
                } else {
                    atomicAdd(&g_histB[b][k & 0xFFFFu], 1u);
                    unsigned sq = atomicAdd(&g_scnt[b], 1u);
                    if (sq < STASH) g_stash[b][sq] = pk;
                }
            }
        }
    }
}

// ---------------- K4: select low threshold + finish collect from stash -----
__global__ void __launch_bounds__(1024) k_selfin() {
    int b = blockIdx.x, t = threadIdx.x;
    __shared__ unsigned sh_thr, sh_d;
    suffix_select(g_histB[b], g_krem[b], &sh_thr, &sh_d);
    __syncthreads();
    unsigned thr = sh_thr;
    unsigned n = g_scnt[b]; if (n > STASH) n = STASH;
    for (unsigned q = t; q < n; q += 1024) {
        unsigned long long pk = g_stash[b][q];
        if (((unsigned)(pk >> 32) & 0xFFFFu) >= thr) {
            unsigned pos = atomicAdd(&g_cnt[b], 1u);
            if (pos < CAND) g_cand[b][pos] = pk;
        }
    }
}

// ---------------- K5: rank candidates (exact) + gather + deparametrize -----
__global__ void __launch_bounds__(128) k_rankgather(const float* __restrict__ bboxes) {
    int b = blockIdx.y;
    int slot = blockIdx.x * 128 + threadIdx.x;         // 0..4095
    unsigned long long mine = g_cand[b][slot];
    __shared__ unsigned long long scnd[128];
    unsigned rank = 0;
    for (int c0 = 0; c0 < CAND; c0 += 128) {
        __syncthreads();
        scnd[threadIdx.x] = g_cand[b][c0 + threadIdx.x];
        __syncthreads();
#pragma unroll
        for (int j = 0; j < 128; j++) rank += (scnd[j] > mine) ? 1u : 0u;
    }
    if (mine == 0ull || rank >= TOPK) return;          // padding or beyond top-k
    int i = (int)rank;
    unsigned key = (unsigned)(mine >> 32);
    unsigned idx = ~(unsigned)(mine & 0xFFFFFFFFull);
    g_sc[b][i] = fromkey(key);
    int z = idx / 9216, r = idx % 9216, y = r / 96, x = r % 96;
    long base = (long)b * 6 * NSP + idx;
    float czyx[3] = { (float)z + 0.5f, (float)y + 0.5f, (float)x + 0.5f };
    float c3[3], s3[3];
#pragma unroll
    for (int c = 0; c < 3; c++) {
        c3[c] = bboxes[base + (long)c * NSP] * ANCH + czyx[c];
        g_bx[b][i][c] = c3[c];
    }
#pragma unroll
    for (int c = 0; c < 3; c++) {
        s3[c] = expf(bboxes[base + (long)(c + 3) * NSP]) * ANCH;
        g_bx[b][i][c + 3] = s3[c];
    }
    float4 L = make_float4(c3[0] - 0.5f * s3[0], c3[1] - 0.5f * s3[1],
                           c3[2] - 0.5f * s3[2], c3[0] + 0.5f * s3[0]);
    float4 H = make_float4(c3[1] + 0.5f * s3[1], c3[2] + 0.5f * s3[2],
                           s3[0] * s3[1] * s3[2], 0.0f);
    ((float4*)g_pb[b][i])[0] = L;
    ((float4*)g_pb[b][i])[1] = H;
}

// ---------------- K6: IoU bitmask + replay-state cleanup -------------------
__global__ void __launch_bounds__(128) k_iou() {
    int b = blockIdx.z, rbk = blockIdx.y, cb = blockIdx.x, t = threadIdx.x;
    // cleanup tail for next graph replay: zero hists + cand + counters
    {
        unsigned flat = ((blockIdx.z * gridDim.y + blockIdx.y) * gridDim.x + blockIdx.x) * 128u + t;
        for (unsigned u = flat; u < 139264u; u += 65536u) {     // u64 slots
            if (u < 65536u)       ((unsigned long long*)g_histA)[u] = 0ull;
            else if (u < 131072u) ((unsigned long long*)g_histB)[u - 65536u] = 0ull;
            else                  ((unsigned long long*)g_cand)[u - 131072u] = 0ull;
        }
        if (flat < BATCH) { g_cnt[flat] = 0u; g_scnt[flat] = 0u; }
    }
    int row0 = rbk << 8;
    int c0 = cb << 6;
    if (c0 + 63 <= row0) return;                       // tile entirely below diag
    __shared__ float4 scol[64][2];
    { int j = t >> 1, h = t & 1; scol[j][h] = ((const float4*)g_pb[b][c0 + j])[h]; }
    __syncthreads();
    int r1 = row0 + t, r2 = row0 + 128 + t;
    float4 aL = ((const float4*)g_pb[b][r1])[0];
    float4 aH = ((const float4*)g_pb[b][r1])[1];
    float4 bL = ((const float4*)g_pb[b][r2])[0];
    float4 bH = ((const float4*)g_pb[b][r2])[1];
    unsigned a0 = 0u, a1 = 0u, b0 = 0u, b1 = 0u;
#pragma unroll
    for (int j = 0; j < 64; j++) {
        float4 cL = scol[j][0], cH = scol[j][1];
        float e0 = fmaxf(fminf(aL.w, cL.w) - fmaxf(aL.x, cL.x), 0.0f);
        float e1 = fmaxf(fminf(aH.x, cH.x) - fmaxf(aL.y, cL.y), 0.0f);
        float e2 = fmaxf(fminf(aH.y, cH.y) - fmaxf(aL.z, cL.z), 0.0f);
        float inter1 = e0 * e1 * e2;
        bool p1 = (5.0f * inter1 > aH.z + cH.z);
        float f0 = fmaxf(fminf(bL.w, cL.w) - fmaxf(bL.x, cL.x), 0.0f);
        float f1 = fmaxf(fminf(bH.x, cH.x) - fmaxf(bL.y, cL.y), 0.0f);
        float f2 = fmaxf(fminf(bH.y, cH.y) - fmaxf(bL.z, cL.z), 0.0f);
        float inter2 = f0 * f1 * f2;
        bool p2 = (5.0f * inter2 > bH.z + cH.z);
        unsigned bb = 1u << (j & 31);
        if (j < 32) { if (p1) a0 |= bb; if (p2) b0 |= bb; }
        else        { if (p1) a1 |= bb; if (p2) b1 |= bb; }
    }
    unsigned long long bits1 = (unsigned long long)a0 | ((unsigned long long)a1 << 32);
    unsigned long long bits2 = (unsigned long long)b0 | ((unsigned long long)b1 << 32);
    if (c0 + 63 > r1) {
        if (r1 >= c0) { int k = r1 - c0; bits1 &= (~0ull) << (k + 1); }
        g_mask[b][r1][cb] = bits1;
    }
    if (c0 + 63 > r2) {
        if (r2 >= c0) { int k = r2 - c0; bits2 &= (~0ull) << (k + 1); }
        g_mask[b][r2][cb] = bits2;
    }
}

// ---------------- K7: sequential greedy NMS (LDS-broadcast chain) ----------
__global__ void __launch_bounds__(1024) k_nms(float* __restrict__ out) {
    int b = blockIdx.x, tid = threadIdx.x;
    __shared__ unsigned long long s_rows[2][64][32];
    __shared__ unsigned long long s_remv[32];
    unsigned long long remv = 0ull;

    if (tid >= 32) {                                   // preload chunk 0 (64 rows)
        for (int k = tid - 32; k < 2048; k += 992) {
            s_rows[0][k >> 5][k & 31] = g_mask[b][k >> 5][k & 31];
        }
    }
    __syncthreads();

    for (int c = 0; c < 32; c++) {                     // 32 chunks of 64 rows
        int cur = c & 1;
        if (tid >= 32 && c < 31) {
            int nb = cur ^ 1;
            for (int k = tid - 32; k < 2048; k += 992) {
                s_rows[nb][k >> 5][k & 31] = g_mask[b][((c + 1) << 6) + (k >> 5)][k & 31];
            }
        }
        if (tid < 32) {
            unsigned long long local = __shfl_sync(0xffffffffu, remv, c);
#pragma unroll
            for (int rr = 0; rr < 64; rr++) {
                int i = (c << 6) + rr;
                unsigned long long rdat = s_rows[cur][rr][tid];
                unsigned long long rloc = s_rows[cur][rr][c];   // broadcast LDS, off-chain
                if (64 * tid + 63 <= i) rdat = 0ull;            // mask unwritten words
                unsigned long long m =
                    (unsigned long long)((long long)(local << (63 - rr)) >> 63);
                remv |= rdat & ~m;
                local |= rloc & ~m;
            }
        }
        __syncthreads();
    }
    if (tid < 32) s_remv[tid] = remv;
    __syncthreads();

#pragma unroll
    for (int m = 0; m < 2; m++) {
        int i = m * 1024 + tid;
        bool keep = !((s_remv[i >> 6] >> (i & 63)) & 1ull);
        float* o = out + ((long)b * TOPK + i) * 7;
        o[0] = keep ? g_sc[b][i] : 0.0f;
#pragma unroll
        for (int c = 0; c < 6; c++) o[1 + c] = keep ? g_bx[b][i][c] : 0.0f;
    }
}

// ---------------- launch ---------------------------------------------------
extern "C" void kernel_launch(void* const* d_in, const int* in_sizes, int n_in,
                              void* d_out, int out_size) {
    const float* bboxes = (const float*)d_in[0];   // (2,6,64,96,96)
    const float* scores = (const float*)d_in[1];   // (2,64,96,96)
    float* out = (float*)d_out;                    // (2,2048,7)

    dim3 g16(Q4 / 256, BATCH);                     // 144 x 2
    k_hist1<<<g16, 256>>>(scores);
    k_sel1<<<BATCH, 1024>>>();
    k_pass2<<<g16, 256>>>(scores);
    k_selfin<<<BATCH, 1024>>>();
    k_rankgather<<<dim3(32, BATCH), 128>>>(bboxes);
    k_iou<<<dim3(32, 8, BATCH), 128>>>();
    k_nms<<<BATCH, 1024>>>(out);
}

// round 6
// speedup vs baseline: 1.9423x; 1.0967x over previous
#include <cuda_runtime.h>
#include <math.h>

#define NSP   589824   // 64*96*96
#define BATCH 2
#define TOPK  2048
#define CAND  2048     // count(prefix > P) < 2048 by construction
#define STASH 16384
#define ANCH  12.0f
#define Q4    36864    // NSP/16 : float4 slots per pass chunk

// ---------------- device scratch (zero-initialized at load; re-zeroed each
// replay by k_iou's cleanup tail so the graph is replay-stable) -------------
__device__ __align__(16) unsigned g_histA[BATCH][65536];
__device__ unsigned g_prefix[BATCH];
__device__ unsigned g_cnt[BATCH];
__device__ unsigned g_scnt[BATCH];
__device__ __align__(16) unsigned long long g_cand[BATCH][CAND];
__device__ __align__(16) unsigned long long g_stash[BATCH][STASH];
__device__ float    g_sc[BATCH][TOPK];
__device__ float    g_bx[BATCH][TOPK][6];
__device__ __align__(16) float g_pb[BATCH][TOPK][8];  // lo0,lo1,lo2,hi0 | hi1,hi2,vol,0
__device__ __align__(16) unsigned long long g_mask[BATCH][TOPK][32]; // junk masked in k_nms

__device__ __forceinline__ unsigned fkey(float f) {
    unsigned u = __float_as_uint(f);
    return (u & 0x80000000u) ? ~u : (u | 0x80000000u);
}
__device__ __forceinline__ float fromkey(unsigned k) {
    unsigned u = (k & 0x80000000u) ? (k ^ 0x80000000u) : ~k;
    return __uint_as_float(u);
}

// ---------------- K1: histogram of upper 16 key bits (MLP=4) ---------------
__global__ void k_hist1(const float* __restrict__ scores) {
    int b = blockIdx.y;
    int t = blockIdx.x * blockDim.x + threadIdx.x;        // 0..Q4-1
    const float4* p = (const float4*)(scores + (long)b * NSP);
    float4 v0 = p[t], v1 = p[t + Q4], v2 = p[t + 2 * Q4], v3 = p[t + 3 * Q4];
    float vv[16] = { v0.x,v0.y,v0.z,v0.w, v1.x,v1.y,v1.z,v1.w,
                     v2.x,v2.y,v2.z,v2.w, v3.x,v3.y,v3.z,v3.w };
#pragma unroll
    for (int q = 0; q < 16; q++) atomicAdd(&g_histA[b][fkey(vv[q]) >> 16], 1u);
}

// ---------------- K2: find prefix bin P (2-barrier shfl suffix scan) -------
__global__ void __launch_bounds__(1024) k_sel1() {
    int b = blockIdx.x;
    const unsigned* hist = g_histA[b];
    __shared__ unsigned warptot[32];
    __shared__ unsigned warpabove[32];
    int t = threadIdx.x, lane = t & 31, wid = t >> 5;
    const uint4* h4 = (const uint4*)hist + t * 16;
    unsigned local = 0;
#pragma unroll
    for (int j = 0; j < 16; j++) {
        uint4 v = h4[j];
        local += v.x + v.y + v.z + v.w;
    }
    unsigned suf = local;                         // suffix-incl within warp
#pragma unroll
    for (int off = 1; off < 32; off <<= 1) {
        unsigned v = __shfl_down_sync(0xffffffffu, suf, off);
        if (lane + off < 32) suf += v;
    }
    if (lane == 0) warptot[wid] = suf;
    __syncthreads();
    if (wid == 0) {
        unsigned w = warptot[lane], ws = w;
#pragma unroll
        for (int off = 1; off < 32; off <<= 1) {
            unsigned v = __shfl_down_sync(0xffffffffu, ws, off);
            if (lane + off < 32) ws += v;
        }
        warpabove[lane] = ws - w;                 // strictly above this warp
    }
    __syncthreads();
    unsigned T = warpabove[wid] + (suf - local);  // strictly above my 64 bins
    if (T < TOPK && T + local >= TOPK) {          // unique owner
        unsigned acc = T, P = 0;
        int found = 0;
        for (int j = 15; j >= 0; j--) {
            uint4 v = h4[j];
            unsigned hv[4] = { v.w, v.z, v.y, v.x };
#pragma unroll
            for (int q = 0; q < 4; q++) {
                if (!found) {
                    if (acc + hv[q] >= TOPK) { P = (unsigned)(t*64 + 4*j + (3-q)); found = 1; }
                    else acc += hv[q];
                }
            }
        }
        g_prefix[b] = P;
    }
}

// ---------------- K3: collect prefix>P to cand; prefix==P to stash ---------
__global__ void k_pass2(const float* __restrict__ scores) {
    int b = blockIdx.y;
    int t = blockIdx.x * blockDim.x + threadIdx.x;        // 0..Q4-1
    unsigned pref = g_prefix[b];
    const float4* p = (const float4*)(scores + (long)b * NSP);
    float4 v[4] = { p[t], p[t + Q4], p[t + 2 * Q4], p[t + 3 * Q4] };
#pragma unroll
    for (int kk = 0; kk < 4; kk++) {
        float vv[4] = { v[kk].x, v[kk].y, v[kk].z, v[kk].w };
#pragma unroll
        for (int q = 0; q < 4; q++) {
            unsigned k = fkey(vv[q]);
            unsigned pp = k >> 16;
            if (pp >= pref) {
                unsigned idx = (unsigned)((t + kk * Q4) * 4 + q);
                unsigned long long pk = ((unsigned long long)k << 32) | (unsigned)(~idx);
                if (pp > pref) {
                    unsigned pos = atomicAdd(&g_cnt[b], 1u);
                    if (pos < CAND) g_cand[b][pos] = pk;
                } else {
                    unsigned sq = atomicAdd(&g_scnt[b], 1u);
                    if (sq < STASH) g_stash[b][sq] = pk;
                }
            }
        }
    }
}

// ---------------- K4: exact rank of cand ∪ stash + gather + deparametrize --
__global__ void __launch_bounds__(128) k_rankgather(const float* __restrict__ bboxes) {
    int b = blockIdx.y;
    int slot = blockIdx.x * 128 + threadIdx.x;            // 0..CAND+STASH-1
    unsigned cnt  = g_cnt[b];  if (cnt  > CAND)  cnt  = CAND;
    unsigned scnt = g_scnt[b]; if (scnt > STASH) scnt = STASH;
    bool active = false;
    unsigned long long mine = 0ull;
    if ((unsigned)slot < cnt) { mine = g_cand[b][slot]; active = true; }
    else if (slot >= CAND && (unsigned)(slot - CAND) < scnt) {
        mine = g_stash[b][slot - CAND]; active = true;
    }
    // blocks entirely past both regions exit before any sync
    if ((unsigned)(blockIdx.x * 128) >= cnt && blockIdx.x * 128 < CAND) {
        // mixed/empty cand-region block: keep threads for syncs
    }
    if (blockIdx.x * 128 >= CAND && (unsigned)(blockIdx.x * 128 - CAND) >= scnt) return;

    __shared__ unsigned long long scnd[128];
    unsigned rank = 0;
    for (unsigned c0 = 0; c0 < cnt; c0 += 128) {
        __syncthreads();
        scnd[threadIdx.x] = (c0 + threadIdx.x < cnt) ? g_cand[b][c0 + threadIdx.x] : 0ull;
        __syncthreads();
#pragma unroll 16
        for (int j = 0; j < 128; j++) rank += (scnd[j] > mine) ? 1u : 0u;
    }
    for (unsigned c0 = 0; c0 < scnt; c0 += 128) {
        __syncthreads();
        scnd[threadIdx.x] = (c0 + threadIdx.x < scnt) ? g_stash[b][c0 + threadIdx.x] : 0ull;
        __syncthreads();
#pragma unroll 16
        for (int j = 0; j < 128; j++) rank += (scnd[j] > mine) ? 1u : 0u;
    }
    if (!active || rank >= TOPK) return;
    int i = (int)rank;
    unsigned key = (unsigned)(mine >> 32);
    unsigned idx = ~(unsigned)(mine & 0xFFFFFFFFull);
    g_sc[b][i] = fromkey(key);
    int z = idx / 9216, r = idx % 9216, y = r / 96, x = r % 96;
    long base = (long)b * 6 * NSP + idx;
    float czyx[3] = { (float)z + 0.5f, (float)y + 0.5f, (float)x + 0.5f };
    float c3[3], s3[3];
#pragma unroll
    for (int c = 0; c < 3; c++) {
        c3[c] = bboxes[base + (long)c * NSP] * ANCH + czyx[c];
        g_bx[b][i][c] = c3[c];
    }
#pragma unroll
    for (int c = 0; c < 3; c++) {
        s3[c] = expf(bboxes[base + (long)(c + 3) * NSP]) * ANCH;
        g_bx[b][i][c + 3] = s3[c];
    }
    float4 L = make_float4(c3[0] - 0.5f * s3[0], c3[1] - 0.5f * s3[1],
                           c3[2] - 0.5f * s3[2], c3[0] + 0.5f * s3[0]);
    float4 H = make_float4(c3[1] + 0.5f * s3[1], c3[2] + 0.5f * s3[2],
                           s3[0] * s3[1] * s3[2], 0.0f);
    ((float4*)g_pb[b][i])[0] = L;
    ((float4*)g_pb[b][i])[1] = H;
}

// ---------------- K5: IoU bitmask + replay-state cleanup -------------------
__global__ void __launch_bounds__(128) k_iou() {
    int b = blockIdx.z, rbk = blockIdx.y, cb = blockIdx.x, t = threadIdx.x;
    // cleanup for next graph replay: zero histA + counters (1 store/thread)
    {
        unsigned flat = ((blockIdx.z * gridDim.y + blockIdx.y) * gridDim.x + blockIdx.x) * 128u + t;
        if (flat < 65536u) ((unsigned long long*)g_histA)[flat] = 0ull;
        if (flat < BATCH) { g_cnt[flat] = 0u; g_scnt[flat] = 0u; }
    }
    int row0 = rbk << 8;
    int c0 = cb << 6;
    if (c0 + 63 <= row0) return;                       // tile entirely below diag
    __shared__ float4 scol[64][2];
    { int j = t >> 1, h = t & 1; scol[j][h] = ((const float4*)g_pb[b][c0 + j])[h]; }
    __syncthreads();
    int r1 = row0 + t, r2 = row0 + 128 + t;
    float4 aL = ((const float4*)g_pb[b][r1])[0];
    float4 aH = ((const float4*)g_pb[b][r1])[1];
    float4 bL = ((const float4*)g_pb[b][r2])[0];
    float4 bH = ((const float4*)g_pb[b][r2])[1];
    unsigned a0 = 0u, a1 = 0u, b0 = 0u, b1 = 0u;
#pragma unroll
    for (int j = 0; j < 64; j++) {
        float4 cL = scol[j][0], cH = scol[j][1];
        float e0 = fmaxf(fminf(aL.w, cL.w) - fmaxf(aL.x, cL.x), 0.0f);
        float e1 = fmaxf(fminf(aH.x, cH.x) - fmaxf(aL.y, cL.y), 0.0f);
        float e2 = fmaxf(fminf(aH.y, cH.y) - fmaxf(aL.z, cL.z), 0.0f);
        float inter1 = e0 * e1 * e2;
        bool p1 = (5.0f * inter1 > aH.z + cH.z);
        float f0 = fmaxf(fminf(bL.w, cL.w) - fmaxf(bL.x, cL.x), 0.0f);
        float f1 = fmaxf(fminf(bH.x, cH.x) - fmaxf(bL.y, cL.y), 0.0f);
        float f2 = fmaxf(fminf(bH.y, cH.y) - fmaxf(bL.z, cL.z), 0.0f);
        float inter2 = f0 * f1 * f2;
        bool p2 = (5.0f * inter2 > bH.z + cH.z);
        unsigned bb = 1u << (j & 31);
        if (j < 32) { if (p1) a0 |= bb; if (p2) b0 |= bb; }
        else        { if (p1) a1 |= bb; if (p2) b1 |= bb; }
    }
    unsigned long long bits1 = (unsigned long long)a0 | ((unsigned long long)a1 << 32);
    unsigned long long bits2 = (unsigned long long)b0 | ((unsigned long long)b1 << 32);
    if (c0 + 63 > r1) {
        if (r1 >= c0) { int k = r1 - c0; bits1 &= (~0ull) << (k + 1); }
        g_mask[b][r1][cb] = bits1;
    }
    if (c0 + 63 > r2) {
        if (r2 >= c0) { int k = r2 - c0; bits2 &= (~0ull) << (k + 1); }
        g_mask[b][r2][cb] = bits2;
    }
}

// ---------------- K6: sequential greedy NMS (LDS-broadcast chain) ----------
__global__ void __launch_bounds__(1024) k_nms(float* __restrict__ out) {
    int b = blockIdx.x, tid = threadIdx.x;
    __shared__ unsigned long long s_rows[2][64][32];
    __shared__ unsigned long long s_remv[32];
    unsigned long long remv = 0ull;

    if (tid >= 32) {                                   // preload chunk 0 (64 rows)
        for (int k = tid - 32; k < 2048; k += 992) {
            s_rows[0][k >> 5][k & 31] = g_mask[b][k >> 5][k & 31];
        }
    }
    __syncthreads();

    for (int c = 0; c < 32; c++) {                     // 32 chunks of 64 rows
        int cur = c & 1;
        if (tid >= 32 && c < 31) {
            int nb = cur ^ 1;
            for (int k = tid - 32; k < 2048; k += 992) {
                s_rows[nb][k >> 5][k & 31] = g_mask[b][((c + 1) << 6) + (k >> 5)][k & 31];
            }
        }
        if (tid < 32) {
            unsigned long long local = __shfl_sync(0xffffffffu, remv, c);
#pragma unroll
            for (int rr = 0; rr < 64; rr++) {
                int i = (c << 6) + rr;
                unsigned long long rdat = s_rows[cur][rr][tid];
                unsigned long long rloc = s_rows[cur][rr][c];   // broadcast LDS, off-chain
                if (64 * tid + 63 <= i) rdat = 0ull;            // mask unwritten words
                unsigned long long m =
                    (unsigned long long)((long long)(local << (63 - rr)) >> 63);
                remv |= rdat & ~m;
                local |= rloc & ~m;
            }
        }
        __syncthreads();
    }
    if (tid < 32) s_remv[tid] = remv;
    __syncthreads();

#pragma unroll
    for (int m = 0; m < 2; m++) {
        int i = m * 1024 + tid;
        bool keep = !((s_remv[i >> 6] >> (i & 63)) & 1ull);
        float* o = out + ((long)b * TOPK + i) * 7;
        o[0] = keep ? g_sc[b][i] : 0.0f;
#pragma unroll
        for (int c = 0; c < 6; c++) o[1 + c] = keep ? g_bx[b][i][c] : 0.0f;
    }
}

// ---------------- launch ---------------------------------------------------
extern "C" void kernel_launch(void* const* d_in, const int* in_sizes, int n_in,
                              void* d_out, int out_size) {
    const float* bboxes = (const float*)d_in[0];   // (2,6,64,96,96)
    const float* scores = (const float*)d_in[1];   // (2,64,96,96)
    float* out = (float*)d_out;                    // (2,2048,7)

    dim3 g16(Q4 / 256, BATCH);                     // 144 x 2
    k_hist1<<<g16, 256>>>(scores);
    k_sel1<<<BATCH, 1024>>>();
    k_pass2<<<g16, 256>>>(scores);
    k_rankgather<<<dim3((CAND + STASH) / 128, BATCH), 128>>>(bboxes);
    k_iou<<<dim3(32, 8, BATCH), 128>>>();
    k_nms<<<BATCH, 1024>>>(out);
}

// round 7
// speedup vs baseline: 2.1700x; 1.1172x over previous
#include <cuda_runtime.h>
#include <math.h>

#define NSP   589824   // 64*96*96
#define BATCH 2
#define TOPK  2048
#define CAND  2048     // count(prefix > P) < 2048 by construction
#define STASH 16384
#define ANCH  12.0f
#define Q4    36864    // NSP/16 : float4 slots per pass chunk

// ---------------- device scratch (zero-initialized at load; re-zeroed each
// replay by k_iou's cleanup tail so the graph is replay-stable) -------------
__device__ __align__(16) unsigned g_histA[BATCH][65536];
__device__ unsigned g_prefix[BATCH];
__device__ unsigned g_cnt[BATCH];
__device__ unsigned g_scnt[BATCH];
__device__ __align__(16) unsigned long long g_cand[BATCH][CAND];
__device__ __align__(16) unsigned long long g_stash[BATCH][STASH];
__device__ float    g_sc[BATCH][TOPK];
__device__ float    g_bx[BATCH][TOPK][6];
__device__ __align__(16) float g_pb[BATCH][TOPK][8];  // lo0,lo1,lo2,hi0 | hi1,hi2,vol,0
__device__ __align__(16) unsigned long long g_mask[BATCH][TOPK][32]; // junk masked in k_nms

__device__ __forceinline__ unsigned fkey(float f) {
    unsigned u = __float_as_uint(f);
    return (u & 0x80000000u) ? ~u : (u | 0x80000000u);
}
__device__ __forceinline__ float fromkey(unsigned k) {
    unsigned u = (k & 0x80000000u) ? (k ^ 0x80000000u) : ~k;
    return __uint_as_float(u);
}

// ---------------- K1: histogram of upper 16 key bits (MLP=4) ---------------
__global__ void k_hist1(const float* __restrict__ scores) {
    int b = blockIdx.y;
    int t = blockIdx.x * blockDim.x + threadIdx.x;        // 0..Q4-1
    const float4* p = (const float4*)(scores + (long)b * NSP);
    float4 v0 = p[t], v1 = p[t + Q4], v2 = p[t + 2 * Q4], v3 = p[t + 3 * Q4];
    float vv[16] = { v0.x,v0.y,v0.z,v0.w, v1.x,v1.y,v1.z,v1.w,
                     v2.x,v2.y,v2.z,v2.w, v3.x,v3.y,v3.z,v3.w };
#pragma unroll
    for (int q = 0; q < 16; q++) atomicAdd(&g_histA[b][fkey(vv[q]) >> 16], 1u);
}

// ---------------- K2: find prefix bin P (2-barrier shfl suffix scan) -------
__global__ void __launch_bounds__(1024) k_sel1() {
    int b = blockIdx.x;
    const unsigned* hist = g_histA[b];
    __shared__ unsigned warptot[32];
    __shared__ unsigned warpabove[32];
    int t = threadIdx.x, lane = t & 31, wid = t >> 5;
    const uint4* h4 = (const uint4*)hist + t * 16;
    unsigned local = 0;
#pragma unroll
    for (int j = 0; j < 16; j++) {
        uint4 v = h4[j];
        local += v.x + v.y + v.z + v.w;
    }
    unsigned suf = local;                         // suffix-incl within warp
#pragma unroll
    for (int off = 1; off < 32; off <<= 1) {
        unsigned v = __shfl_down_sync(0xffffffffu, suf, off);
        if (lane + off < 32) suf += v;
    }
    if (lane == 0) warptot[wid] = suf;
    __syncthreads();
    if (wid == 0) {
        unsigned w = warptot[lane], ws = w;
#pragma unroll
        for (int off = 1; off < 32; off <<= 1) {
            unsigned v = __shfl_down_sync(0xffffffffu, ws, off);
            if (lane + off < 32) ws += v;
        }
        warpabove[lane] = ws - w;                 // strictly above this warp
    }
    __syncthreads();
    unsigned T = warpabove[wid] + (suf - local);  // strictly above my 64 bins
    if (T < TOPK && T + local >= TOPK) {          // unique owner
        unsigned acc = T, P = 0;
        int found = 0;
        for (int j = 15; j >= 0; j--) {
            uint4 v = h4[j];
            unsigned hv[4] = { v.w, v.z, v.y, v.x };
#pragma unroll
            for (int q = 0; q < 4; q++) {
                if (!found) {
                    if (acc + hv[q] >= TOPK) { P = (unsigned)(t*64 + 4*j + (3-q)); found = 1; }
                    else acc += hv[q];
                }
            }
        }
        g_prefix[b] = P;
    }
}

// ---------------- K3: collect prefix>P to cand; prefix==P to stash ---------
__global__ void k_pass2(const float* __restrict__ scores) {
    int b = blockIdx.y;
    int t = blockIdx.x * blockDim.x + threadIdx.x;        // 0..Q4-1
    unsigned pref = g_prefix[b];
    const float4* p = (const float4*)(scores + (long)b * NSP);
    float4 v[4] = { p[t], p[t + Q4], p[t + 2 * Q4], p[t + 3 * Q4] };
#pragma unroll
    for (int kk = 0; kk < 4; kk++) {
        float vv[4] = { v[kk].x, v[kk].y, v[kk].z, v[kk].w };
#pragma unroll
        for (int q = 0; q < 4; q++) {
            unsigned k = fkey(vv[q]);
            unsigned pp = k >> 16;
            if (pp >= pref) {
                unsigned idx = (unsigned)((t + kk * Q4) * 4 + q);
                unsigned long long pk = ((unsigned long long)k << 32) | (unsigned)(~idx);
                if (pp > pref) {
                    unsigned pos = atomicAdd(&g_cnt[b], 1u);
                    if (pos < CAND) g_cand[b][pos] = pk;
                } else {
                    unsigned sq = atomicAdd(&g_scnt[b], 1u);
                    if (sq < STASH) g_stash[b][sq] = pk;
                }
            }
        }
    }
}

// ---------------- K4: warp-per-candidate rank + gather + deparametrize -----
__device__ __forceinline__ void emit_box(int b, unsigned long long mine, unsigned rank,
                                         const float* __restrict__ bboxes) {
    if (rank >= TOPK) return;
    int i = (int)rank;
    unsigned key = (unsigned)(mine >> 32);
    unsigned idx = ~(unsigned)(mine & 0xFFFFFFFFull);
    g_sc[b][i] = fromkey(key);
    int z = idx / 9216, r = idx % 9216, y = r / 96, x = r % 96;
    long base = (long)b * 6 * NSP + idx;
    float czyx[3] = { (float)z + 0.5f, (float)y + 0.5f, (float)x + 0.5f };
    float c3[3], s3[3];
#pragma unroll
    for (int c = 0; c < 3; c++) {
        c3[c] = bboxes[base + (long)c * NSP] * ANCH + czyx[c];
        g_bx[b][i][c] = c3[c];
    }
#pragma unroll
    for (int c = 0; c < 3; c++) {
        s3[c] = expf(bboxes[base + (long)(c + 3) * NSP]) * ANCH;
        g_bx[b][i][c + 3] = s3[c];
    }
    float4 L = make_float4(c3[0] - 0.5f * s3[0], c3[1] - 0.5f * s3[1],
                           c3[2] - 0.5f * s3[2], c3[0] + 0.5f * s3[0]);
    float4 H = make_float4(c3[1] + 0.5f * s3[1], c3[2] + 0.5f * s3[2],
                           s3[0] * s3[1] * s3[2], 0.0f);
    ((float4*)g_pb[b][i])[0] = L;
    ((float4*)g_pb[b][i])[1] = H;
}

__global__ void __launch_bounds__(256) k_rankgather(const float* __restrict__ bboxes) {
    int b = blockIdx.y, bx = blockIdx.x;
    int t = threadIdx.x, lane = t & 31, w = t >> 5;
    unsigned cnt  = g_cnt[b];  if (cnt  > CAND)  cnt  = CAND;
    unsigned scnt = g_scnt[b]; if (scnt > STASH) scnt = STASH;

    if (bx < 256) {
        // ---- cand slots: every cand key > every stash key, rank among cand only
        __shared__ unsigned long long sc[CAND];
#pragma unroll
        for (int m = 0; m < 8; m++) sc[m * 256 + t] = g_cand[b][m * 256 + t];
        __syncthreads();
        unsigned slot = bx * 8 + (unsigned)w;          // one slot per warp
        if (slot >= cnt) return;                       // warp-uniform
        unsigned long long mine = sc[slot];
        unsigned c = 0;
#pragma unroll 4
        for (unsigned j = lane; j < cnt; j += 32) c += (sc[j] > mine) ? 1u : 0u;
        unsigned rank = __reduce_add_sync(0xffffffffu, c);
        if (lane == 0) emit_box(b, mine, rank, bboxes);
    } else {
        // ---- stash slots: rank = cnt + rank-within-stash
        for (unsigned slot = (bx - 256) * 8 + (unsigned)w; slot < scnt; slot += 128) {
            unsigned long long mine = g_stash[b][slot];
            unsigned c = 0;
            for (unsigned j = lane; j < scnt; j += 32)
                c += (g_stash[b][j] > mine) ? 1u : 0u;
            unsigned rank = cnt + __reduce_add_sync(0xffffffffu, c);
            if (lane == 0) emit_box(b, mine, rank, bboxes);
        }
    }
}

// ---------------- K5: IoU bitmask + replay-state cleanup -------------------
__global__ void __launch_bounds__(128) k_iou() {
    int b = blockIdx.z, rbk = blockIdx.y, cb = blockIdx.x, t = threadIdx.x;
    // cleanup for next graph replay: zero histA + counters (1 store/thread)
    {
        unsigned flat = ((blockIdx.z * gridDim.y + blockIdx.y) * gridDim.x + blockIdx.x) * 128u + t;
        if (flat < 65536u) ((unsigned long long*)g_histA)[flat] = 0ull;
        if (flat < BATCH) { g_cnt[flat] = 0u; g_scnt[flat] = 0u; }
    }
    int row0 = rbk << 8;
    int c0 = cb << 6;
    if (c0 + 63 <= row0) return;                       // tile entirely below diag
    __shared__ float4 scol[64][2];
    { int j = t >> 1, h = t & 1; scol[j][h] = ((const float4*)g_pb[b][c0 + j])[h]; }
    __syncthreads();
    int r1 = row0 + t, r2 = row0 + 128 + t;
    float4 aL = ((const float4*)g_pb[b][r1])[0];
    float4 aH = ((const float4*)g_pb[b][r1])[1];
    float4 bL = ((const float4*)g_pb[b][r2])[0];
    float4 bH = ((const float4*)g_pb[b][r2])[1];
    unsigned a0 = 0u, a1 = 0u, b0 = 0u, b1 = 0u;
#pragma unroll
    for (int j = 0; j < 64; j++) {
        float4 cL = scol[j][0], cH = scol[j][1];
        float e0 = fmaxf(fminf(aL.w, cL.w) - fmaxf(aL.x, cL.x), 0.0f);
        float e1 = fmaxf(fminf(aH.x, cH.x) - fmaxf(aL.y, cL.y), 0.0f);
        float e2 = fmaxf(fminf(aH.y, cH.y) - fmaxf(aL.z, cL.z), 0.0f);
        float inter1 = e0 * e1 * e2;
        bool p1 = (5.0f * inter1 > aH.z + cH.z);
        float f0 = fmaxf(fminf(bL.w, cL.w) - fmaxf(bL.x, cL.x), 0.0f);
        float f1 = fmaxf(fminf(bH.x, cH.x) - fmaxf(bL.y, cL.y), 0.0f);
        float f2 = fmaxf(fminf(bH.y, cH.y) - fmaxf(bL.z, cL.z), 0.0f);
        float inter2 = f0 * f1 * f2;
        bool p2 = (5.0f * inter2 > bH.z + cH.z);
        unsigned bb = 1u << (j & 31);
        if (j < 32) { if (p1) a0 |= bb; if (p2) b0 |= bb; }
        else        { if (p1) a1 |= bb; if (p2) b1 |= bb; }
    }
    unsigned long long bits1 = (unsigned long long)a0 | ((unsigned long long)a1 << 32);
    unsigned long long bits2 = (unsigned long long)b0 | ((unsigned long long)b1 << 32);
    if (c0 + 63 > r1) {
        if (r1 >= c0) { int k = r1 - c0; bits1 &= (~0ull) << (k + 1); }
        g_mask[b][r1][cb] = bits1;
    }
    if (c0 + 63 > r2) {
        if (r2 >= c0) { int k = r2 - c0; bits2 &= (~0ull) << (k + 1); }
        g_mask[b][r2][cb] = bits2;
    }
}

// ---------------- K6: sequential greedy NMS (LDS-broadcast chain) ----------
__global__ void __launch_bounds__(1024) k_nms(float* __restrict__ out) {
    int b = blockIdx.x, tid = threadIdx.x;
    __shared__ unsigned long long s_rows[2][64][32];
    __shared__ unsigned long long s_remv[32];
    unsigned long long remv = 0ull;

    if (tid >= 32) {                                   // preload chunk 0 (64 rows)
        for (int k = tid - 32; k < 2048; k += 992) {
            s_rows[0][k >> 5][k & 31] = g_mask[b][k >> 5][k & 31];
        }
    }
    __syncthreads();

    for (int c = 0; c < 32; c++) {                     // 32 chunks of 64 rows
        int cur = c & 1;
        if (tid >= 32 && c < 31) {
            int nb = cur ^ 1;
            for (int k = tid - 32; k < 2048; k += 992) {
                s_rows[nb][k >> 5][k & 31] = g_mask[b][((c + 1) << 6) + (k >> 5)][k & 31];
            }
        }
        if (tid < 32) {
            unsigned long long local = __shfl_sync(0xffffffffu, remv, c);
#pragma unroll
            for (int rr = 0; rr < 64; rr++) {
                int i = (c << 6) + rr;
                unsigned long long rdat = s_rows[cur][rr][tid];
                unsigned long long rloc = s_rows[cur][rr][c];   // broadcast LDS, off-chain
                if (64 * tid + 63 <= i) rdat = 0ull;            // mask unwritten words
                unsigned long long m =
                    (unsigned long long)((long long)(local << (63 - rr)) >> 63);
                remv |= rdat & ~m;
                local |= rloc & ~m;
            }
        }
        __syncthreads();
    }
    if (tid < 32) s_remv[tid] = remv;
    __syncthreads();

#pragma unroll
    for (int m = 0; m < 2; m++) {
        int i = m * 1024 + tid;
        bool keep = !((s_remv[i >> 6] >> (i & 63)) & 1ull);
        float* o = out + ((long)b * TOPK + i) * 7;
        o[0] = keep ? g_sc[b][i] : 0.0f;
#pragma unroll
        for (int c = 0; c < 6; c++) o[1 + c] = keep ? g_bx[b][i][c] : 0.0f;
    }
}

// ---------------- launch ---------------------------------------------------
extern "C" void kernel_launch(void* const* d_in, const int* in_sizes, int n_in,
                              void* d_out, int out_size) {
    const float* bboxes = (const float*)d_in[0];   // (2,6,64,96,96)
    const float* scores = (const float*)d_in[1];   // (2,64,96,96)
    float* out = (float*)d_out;                    // (2,2048,7)

    dim3 g16(Q4 / 256, BATCH);                     // 144 x 2
    k_hist1<<<g16, 256>>>(scores);
    k_sel1<<<BATCH, 1024>>>();
    k_pass2<<<g16, 256>>>(scores);
    k_rankgather<<<dim3(272, BATCH), 256>>>(bboxes);
    k_iou<<<dim3(32, 8, BATCH), 128>>>();
    k_nms<<<BATCH, 1024>>>(out);
}

// round 9
// speedup vs baseline: 3.7367x; 1.7220x over previous
#include <cuda_runtime.h>
#include <math.h>

#define NSP   589824   // 64*96*96
#define BATCH 2
#define TOPK  2048
#define CAND  2048     // count(prefix > P) < 2048 by construction
#define STASH 16384
#define ANCH  12.0f
#define Q4    36864    // NSP/16
#define NBIN  4096     // 12-bit prefix bins

// ---------------- device scratch (zero-initialized at load; re-zeroed each
// replay by k_iou's cleanup tail so the graph is replay-stable) -------------
__device__ __align__(16) unsigned g_histA[BATCH][NBIN];
__device__ unsigned g_prefix[BATCH];
__device__ unsigned g_cnt[BATCH];
__device__ unsigned g_scnt[BATCH];
__device__ __align__(16) unsigned long long g_cand[BATCH][CAND];
__device__ __align__(16) unsigned long long g_stash[BATCH][STASH];
__device__ float    g_sc[BATCH][TOPK];
__device__ float    g_bx[BATCH][TOPK][6];
__device__ __align__(16) float g_pb[BATCH][TOPK][8];  // lo0,lo1,lo2,hi0 | hi1,hi2,vol,0
__device__ __align__(16) unsigned long long g_mask[BATCH][TOPK][32]; // junk masked in k_nms

__device__ __forceinline__ unsigned fkey(float f) {
    unsigned u = __float_as_uint(f);
    return (u & 0x80000000u) ? ~u : (u | 0x80000000u);
}
__device__ __forceinline__ float fromkey(unsigned k) {
    unsigned u = (k & 0x80000000u) ? (k ^ 0x80000000u) : ~k;
    return __uint_as_float(u);
}

// ---------------- K1: smem-privatized 4096-bin histogram -------------------
// grid (144, BATCH) x 256 : each block covers 1024 float4 = 4096 scores
// 144 * 1024 float4 = 147456 float4 = 589824 floats = NSP  (full coverage)
__global__ void __launch_bounds__(256) k_hist1(const float* __restrict__ scores) {
    __shared__ unsigned h[NBIN];
    int b = blockIdx.y, t = threadIdx.x;
#pragma unroll
    for (int i = t; i < NBIN; i += 256) h[i] = 0u;
    __syncthreads();
    const float4* p = (const float4*)(scores + (long)b * NSP) + blockIdx.x * 1024;
    float4 v0 = p[t], v1 = p[256 + t], v2 = p[512 + t], v3 = p[768 + t];
    float vv[16] = { v0.x,v0.y,v0.z,v0.w, v1.x,v1.y,v1.z,v1.w,
                     v2.x,v2.y,v2.z,v2.w, v3.x,v3.y,v3.z,v3.w };
#pragma unroll
    for (int q = 0; q < 16; q++) atomicAdd(&h[fkey(vv[q]) >> 20], 1u);
    __syncthreads();
#pragma unroll
    for (int i = t; i < NBIN; i += 256) {
        unsigned c = h[i];
        if (c) atomicAdd(&g_histA[b][i], c);
    }
}

// ---------------- K2: find prefix bin P over 4096 bins ---------------------
__global__ void __launch_bounds__(1024) k_sel1() {
    int b = blockIdx.x;
    __shared__ unsigned warptot[32];
    __shared__ unsigned warpabove[32];
    int t = threadIdx.x, lane = t & 31, wid = t >> 5;
    uint4 v = ((const uint4*)g_histA[b])[t];          // 4 bins per thread
    unsigned local = v.x + v.y + v.z + v.w;
    unsigned suf = local;                             // suffix-incl within warp
#pragma unroll
    for (int off = 1; off < 32; off <<= 1) {
        unsigned x = __shfl_down_sync(0xffffffffu, suf, off);
        if (lane + off < 32) suf += x;
    }
    if (lane == 0) warptot[wid] = suf;
    __syncthreads();
    if (wid == 0) {
        unsigned w = warptot[lane], ws = w;
#pragma unroll
        for (int off = 1; off < 32; off <<= 1) {
            unsigned x = __shfl_down_sync(0xffffffffu, ws, off);
            if (lane + off < 32) ws += x;
        }
        warpabove[lane] = ws - w;                     // strictly above this warp
    }
    __syncthreads();
    unsigned T = warpabove[wid] + (suf - local);      // strictly above my 4 bins
    if (T < TOPK && T + local >= TOPK) {              // unique owner
        unsigned acc = T, P = 0;
        unsigned hv[4] = { v.w, v.z, v.y, v.x };
        int found = 0;
#pragma unroll
        for (int q = 0; q < 4; q++) {
            if (!found) {
                if (acc + hv[q] >= TOPK) { P = (unsigned)(t * 4 + (3 - q)); found = 1; }
                else acc += hv[q];
            }
        }
        g_prefix[b] = P;
    }
}

// ---------------- K3: collect prefix>P to cand; prefix==P to stash ---------
__global__ void k_pass2(const float* __restrict__ scores) {
    int b = blockIdx.y;
    int t = blockIdx.x * blockDim.x + threadIdx.x;        // 0..Q4-1
    unsigned pref = g_prefix[b];
    const float4* p = (const float4*)(scores + (long)b * NSP);
    float4 v[4] = { p[t], p[t + Q4], p[t + 2 * Q4], p[t + 3 * Q4] };
#pragma unroll
    for (int kk = 0; kk < 4; kk++) {
        float vv[4] = { v[kk].x, v[kk].y, v[kk].z, v[kk].w };
#pragma unroll
        for (int q = 0; q < 4; q++) {
            unsigned k = fkey(vv[q]);
            unsigned pp = k >> 20;
            if (pp >= pref) {
                unsigned idx = (unsigned)((t + kk * Q4) * 4 + q);
                unsigned long long pk = ((unsigned long long)k << 32) | (unsigned)(~idx);
                if (pp > pref) {
                    unsigned pos = atomicAdd(&g_cnt[b], 1u);
                    if (pos < CAND) g_cand[b][pos] = pk;
                } else {
                    unsigned sq = atomicAdd(&g_scnt[b], 1u);
                    if (sq < STASH) g_stash[b][sq] = pk;
                }
            }
        }
    }
}

// ---------------- K4: warp-per-candidate rank + gather + deparametrize -----
__device__ __forceinline__ void emit_box(int b, unsigned long long mine, unsigned rank,
                                         const float* __restrict__ bboxes) {
    if (rank >= TOPK) return;
    int i = (int)rank;
    unsigned key = (unsigned)(mine >> 32);
    unsigned idx = ~(unsigned)(mine & 0xFFFFFFFFull);
    g_sc[b][i] = fromkey(key);
    int z = idx / 9216, r = idx % 9216, y = r / 96, x = r % 96;
    long base = (long)b * 6 * NSP + idx;
    float czyx[3] = { (float)z + 0.5f, (float)y + 0.5f, (float)x + 0.5f };
    float c3[3], s3[3];
#pragma unroll
    for (int c = 0; c < 3; c++) {
        c3[c] = bboxes[base + (long)c * NSP] * ANCH + czyx[c];
        g_bx[b][i][c] = c3[c];
    }
#pragma unroll
    for (int c = 0; c < 3; c++) {
        s3[c] = expf(bboxes[base + (long)(c + 3) * NSP]) * ANCH;
        g_bx[b][i][c + 3] = s3[c];
    }
    float4 L = make_float4(c3[0] - 0.5f * s3[0], c3[1] - 0.5f * s3[1],
                           c3[2] - 0.5f * s3[2], c3[0] + 0.5f * s3[0]);
    float4 H = make_float4(c3[1] + 0.5f * s3[1], c3[2] + 0.5f * s3[2],
                           s3[0] * s3[1] * s3[2], 0.0f);
    ((float4*)g_pb[b][i])[0] = L;
    ((float4*)g_pb[b][i])[1] = H;
}

__global__ void __launch_bounds__(256) k_rankgather(const float* __restrict__ bboxes) {
    int b = blockIdx.y, bx = blockIdx.x;
    int t = threadIdx.x, lane = t & 31, w = t >> 5;
    unsigned cnt  = g_cnt[b];  if (cnt  > CAND)  cnt  = CAND;
    unsigned scnt = g_scnt[b]; if (scnt > STASH) scnt = STASH;

    if (bx < 256) {
        // ---- cand slots: every cand key > every stash key, rank among cand only
        __shared__ unsigned long long sc[CAND];
#pragma unroll
        for (int m = 0; m < 8; m++) sc[m * 256 + t] = g_cand[b][m * 256 + t];
        __syncthreads();
        unsigned slot = bx * 8 + (unsigned)w;          // one slot per warp
        if (slot >= cnt) return;                       // warp-uniform
        unsigned long long mine = sc[slot];
        unsigned c = 0;
#pragma unroll 4
        for (unsigned j = lane; j < cnt; j += 32) c += (sc[j] > mine) ? 1u : 0u;
        unsigned rank = __reduce_add_sync(0xffffffffu, c);
        if (lane == 0) emit_box(b, mine, rank, bboxes);
    } else {
        // ---- stash slots: rank = cnt + rank-within-stash
        for (unsigned slot = (bx - 256) * 8 + (unsigned)w; slot < scnt; slot += 128) {
            unsigned long long mine = g_stash[b][slot];
            unsigned c = 0;
            for (unsigned j = lane; j < scnt; j += 32)
                c += (g_stash[b][j] > mine) ? 1u : 0u;
            unsigned rank = cnt + __reduce_add_sync(0xffffffffu, c);
            if (lane == 0) emit_box(b, mine, rank, bboxes);
        }
    }
}

// ---------------- K5: IoU bitmask + replay-state cleanup -------------------
__global__ void __launch_bounds__(128) k_iou() {
    int b = blockIdx.z, rbk = blockIdx.y, cb = blockIdx.x, t = threadIdx.x;
    // cleanup for next graph replay: zero histA + counters
    {
        unsigned flat = ((blockIdx.z * gridDim.y + blockIdx.y) * gridDim.x + blockIdx.x) * 128u + t;
        if (flat < BATCH * NBIN / 2) ((unsigned long long*)g_histA)[flat] = 0ull;
        if (flat < BATCH) { g_cnt[flat] = 0u; g_scnt[flat] = 0u; }
    }
    int row0 = rbk << 8;
    int c0 = cb << 6;
    if (c0 + 63 <= row0) return;                       // tile entirely below diag
    __shared__ float4 scol[64][2];
    { int j = t >> 1, h = t & 1; scol[j][h] = ((const float4*)g_pb[b][c0 + j])[h]; }
    __syncthreads();
    int r1 = row0 + t, r2 = row0 + 128 + t;
    float4 aL = ((const float4*)g_pb[b][r1])[0];
    float4 aH = ((const float4*)g_pb[b][r1])[1];
    float4 bL = ((const float4*)g_pb[b][r2])[0];
    float4 bH = ((const float4*)g_pb[b][r2])[1];
    unsigned a0 = 0u, a1 = 0u, b0 = 0u, b1 = 0u;
#pragma unroll
    for (int j = 0; j < 64; j++) {
        float4 cL = scol[j][0], cH = scol[j][1];
        float e0 = fmaxf(fminf(aL.w, cL.w) - fmaxf(aL.x, cL.x), 0.0f);
        float e1 = fmaxf(fminf(aH.x, cH.x) - fmaxf(aL.y, cL.y), 0.0f);
        float e2 = fmaxf(fminf(aH.y, cH.y) - fmaxf(aL.z, cL.z), 0.0f);
        float inter1 = e0 * e1 * e2;
        bool p1 = (5.0f * inter1 > aH.z + cH.z);
        float f0 = fmaxf(fminf(bL.w, cL.w) - fmaxf(bL.x, cL.x), 0.0f);
        float f1 = fmaxf(fminf(bH.x, cH.x) - fmaxf(bL.y, cL.y), 0.0f);
        float f2 = fmaxf(fminf(bH.y, cH.y) - fmaxf(bL.z, cL.z), 0.0f);
        float inter2 = f0 * f1 * f2;
        bool p2 = (5.0f * inter2 > bH.z + cH.z);
        unsigned bb = 1u << (j & 31);
        if (j < 32) { if (p1) a0 |= bb; if (p2) b0 |= bb; }
        else        { if (p1) a1 |= bb; if (p2) b1 |= bb; }
    }
    unsigned long long bits1 = (unsigned long long)a0 | ((unsigned long long)a1 << 32);
    unsigned long long bits2 = (unsigned long long)b0 | ((unsigned long long)b1 << 32);
    if (c0 + 63 > r1) {
        if (r1 >= c0) { int k = r1 - c0; bits1 &= (~0ull) << (k + 1); }
        g_mask[b][r1][cb] = bits1;
    }
    if (c0 + 63 > r2) {
        if (r2 >= c0) { int k = r2 - c0; bits2 &= (~0ull) << (k + 1); }
        g_mask[b][r2][cb] = bits2;
    }
}

// ---------------- K6: sequential greedy NMS (LDS-broadcast chain) ----------
__global__ void __launch_bounds__(1024) k_nms(float* __restrict__ out) {
    int b = blockIdx.x, tid = threadIdx.x;
    __shared__ unsigned long long s_rows[2][64][32];
    __shared__ unsigned long long s_remv[32];
    unsigned long long remv = 0ull;

    if (tid >= 32) {                                   // preload chunk 0 (64 rows)
        for (int k = tid - 32; k < 2048; k += 992) {
            s_rows[0][k >> 5][k & 31] = g_mask[b][k >> 5][k & 31];
        }
    }
    __syncthreads();

    for (int c = 0; c < 32; c++) {                     // 32 chunks of 64 rows
        int cur = c & 1;
        if (tid >= 32 && c < 31) {
            int nb = cur ^ 1;
            for (int k = tid - 32; k < 2048; k += 992) {
                s_rows[nb][k >> 5][k & 31] = g_mask[b][((c + 1) << 6) + (k >> 5)][k & 31];
            }
        }
        if (tid < 32) {
            unsigned long long local = __shfl_sync(0xffffffffu, remv, c);
#pragma unroll
            for (int rr = 0; rr < 64; rr++) {
                int i = (c << 6) + rr;
                unsigned long long rdat = s_rows[cur][rr][tid];
                unsigned long long rloc = s_rows[cur][rr][c];   // broadcast LDS, off-chain
                if (64 * tid + 63 <= i) rdat = 0ull;            // mask unwritten words
                unsigned long long m =
                    (unsigned long long)((long long)(local << (63 - rr)) >> 63);
                remv |= rdat & ~m;
                local |= rloc & ~m;
            }
        }
        __syncthreads();
    }
    if (tid < 32) s_remv[tid] = remv;
    __syncthreads();

#pragma unroll
    for (int m = 0; m < 2; m++) {
        int i = m * 1024 + tid;
        bool keep = !((s_remv[i >> 6] >> (i & 63)) & 1ull);
        float* o = out + ((long)b * TOPK + i) * 7;
        o[0] = keep ? g_sc[b][i] : 0.0f;
#pragma unroll
        for (int c = 0; c < 6; c++) o[1 + c] = keep ? g_bx[b][i][c] : 0.0f;
    }
}

// ---------------- launch ---------------------------------------------------
extern "C" void kernel_launch(void* const* d_in, const int* in_sizes, int n_in,
                              void* d_out, int out_size) {
    const float* bboxes = (const float*)d_in[0];   // (2,6,64,96,96)
    const float* scores = (const float*)d_in[1];   // (2,64,96,96)
    float* out = (float*)d_out;                    // (2,2048,7)

    k_hist1<<<dim3(144, BATCH), 256>>>(scores);    // full NSP coverage
    k_sel1<<<BATCH, 1024>>>();
    k_pass2<<<dim3(Q4 / 256, BATCH), 256>>>(scores);
    k_rankgather<<<dim3(272, BATCH), 256>>>(bboxes);
    k_iou<<<dim3(32, 8, BATCH), 128>>>();
    k_nms<<<BATCH, 1024>>>(out);
}

// round 10
// speedup vs baseline: 3.7567x; 1.0053x over previous
#include <cuda_runtime.h>
#include <math.h>

#define NSP   589824   // 64*96*96
#define BATCH 2
#define TOPK  2048
#define CAND  2048     // count(prefix > P) < 2048 by construction
#define STASH 16384
#define ANCH  12.0f
#define Q4    36864    // NSP/16
#define NBIN  4096     // 12-bit prefix bins

// ---------------- device scratch (zero-initialized at load; re-zeroed each
// replay by k_iou's cleanup tail so the graph is replay-stable) -------------
__device__ __align__(16) unsigned g_histA[BATCH][NBIN];
__device__ unsigned g_prefix[BATCH];
__device__ unsigned g_cnt[BATCH];
__device__ unsigned g_scnt[BATCH];
__device__ __align__(16) unsigned long long g_cand[BATCH][CAND];
__device__ __align__(16) unsigned long long g_stash[BATCH][STASH];
__device__ float    g_sc[BATCH][TOPK];
__device__ float    g_bx[BATCH][TOPK][6];
__device__ __align__(16) float g_pb[BATCH][TOPK][8];  // lo0,lo1,lo2,hi0 | hi1,hi2,vol,0
__device__ __align__(16) unsigned long long g_mask[BATCH][TOPK][32]; // junk masked in k_nms

__device__ __forceinline__ unsigned fkey(float f) {
    unsigned u = __float_as_uint(f);
    return (u & 0x80000000u) ? ~u : (u | 0x80000000u);
}
__device__ __forceinline__ float fromkey(unsigned k) {
    unsigned u = (k & 0x80000000u) ? (k ^ 0x80000000u) : ~k;
    return __uint_as_float(u);
}

// ---------------- K1: smem-privatized 4096-bin histogram -------------------
// grid (144, BATCH) x 256 : each block covers 1024 float4 = 4096 scores
__global__ void __launch_bounds__(256) k_hist1(const float* __restrict__ scores) {
    __shared__ unsigned h[NBIN];
    int b = blockIdx.y, t = threadIdx.x;
#pragma unroll
    for (int i = t; i < NBIN; i += 256) h[i] = 0u;
    __syncthreads();
    const float4* p = (const float4*)(scores + (long)b * NSP) + blockIdx.x * 1024;
    float4 v0 = p[t], v1 = p[256 + t], v2 = p[512 + t], v3 = p[768 + t];
    float vv[16] = { v0.x,v0.y,v0.z,v0.w, v1.x,v1.y,v1.z,v1.w,
                     v2.x,v2.y,v2.z,v2.w, v3.x,v3.y,v3.z,v3.w };
#pragma unroll
    for (int q = 0; q < 16; q++) atomicAdd(&h[fkey(vv[q]) >> 20], 1u);
    __syncthreads();
#pragma unroll
    for (int i = t; i < NBIN; i += 256) {
        unsigned c = h[i];
        if (c) atomicAdd(&g_histA[b][i], c);
    }
}

// ---------------- K2: find prefix bin P over 4096 bins ---------------------
__global__ void __launch_bounds__(1024) k_sel1() {
    int b = blockIdx.x;
    __shared__ unsigned warptot[32];
    __shared__ unsigned warpabove[32];
    int t = threadIdx.x, lane = t & 31, wid = t >> 5;
    uint4 v = ((const uint4*)g_histA[b])[t];          // 4 bins per thread
    unsigned local = v.x + v.y + v.z + v.w;
    unsigned suf = local;                             // suffix-incl within warp
#pragma unroll
    for (int off = 1; off < 32; off <<= 1) {
        unsigned x = __shfl_down_sync(0xffffffffu, suf, off);
        if (lane + off < 32) suf += x;
    }
    if (lane == 0) warptot[wid] = suf;
    __syncthreads();
    if (wid == 0) {
        unsigned w = warptot[lane], ws = w;
#pragma unroll
        for (int off = 1; off < 32; off <<= 1) {
            unsigned x = __shfl_down_sync(0xffffffffu, ws, off);
            if (lane + off < 32) ws += x;
        }
        warpabove[lane] = ws - w;                     // strictly above this warp
    }
    __syncthreads();
    unsigned T = warpabove[wid] + (suf - local);      // strictly above my 4 bins
    if (T < TOPK && T + local >= TOPK) {              // unique owner
        unsigned acc = T, P = 0;
        unsigned hv[4] = { v.w, v.z, v.y, v.x };
        int found = 0;
#pragma unroll
        for (int q = 0; q < 4; q++) {
            if (!found) {
                if (acc + hv[q] >= TOPK) { P = (unsigned)(t * 4 + (3 - q)); found = 1; }
                else acc += hv[q];
            }
        }
        g_prefix[b] = P;
    }
}

// ---------------- K3: collect prefix>P to cand; prefix==P to stash ---------
__global__ void k_pass2(const float* __restrict__ scores) {
    int b = blockIdx.y;
    int t = blockIdx.x * blockDim.x + threadIdx.x;        // 0..Q4-1
    unsigned pref = g_prefix[b];
    const float4* p = (const float4*)(scores + (long)b * NSP);
    float4 v[4] = { p[t], p[t + Q4], p[t + 2 * Q4], p[t + 3 * Q4] };
#pragma unroll
    for (int kk = 0; kk < 4; kk++) {
        float vv[4] = { v[kk].x, v[kk].y, v[kk].z, v[kk].w };
#pragma unroll
        for (int q = 0; q < 4; q++) {
            unsigned k = fkey(vv[q]);
            unsigned pp = k >> 20;
            if (pp >= pref) {
                unsigned idx = (unsigned)((t + kk * Q4) * 4 + q);
                unsigned long long pk = ((unsigned long long)k << 32) | (unsigned)(~idx);
                if (pp > pref) {
                    unsigned pos = atomicAdd(&g_cnt[b], 1u);
                    if (pos < CAND) g_cand[b][pos] = pk;
                } else {
                    unsigned sq = atomicAdd(&g_scnt[b], 1u);
                    if (sq < STASH) g_stash[b][sq] = pk;
                }
            }
        }
    }
}

// ---------------- K4: warp-per-candidate rank + gather + deparametrize -----
__device__ __forceinline__ void emit_box(int b, unsigned long long mine, unsigned rank,
                                         const float* __restrict__ bboxes) {
    if (rank >= TOPK) return;
    int i = (int)rank;
    unsigned key = (unsigned)(mine >> 32);
    unsigned idx = ~(unsigned)(mine & 0xFFFFFFFFull);
    g_sc[b][i] = fromkey(key);
    int z = idx / 9216, r = idx % 9216, y = r / 96, x = r % 96;
    long base = (long)b * 6 * NSP + idx;
    float czyx[3] = { (float)z + 0.5f, (float)y + 0.5f, (float)x + 0.5f };
    float c3[3], s3[3];
#pragma unroll
    for (int c = 0; c < 3; c++) {
        c3[c] = bboxes[base + (long)c * NSP] * ANCH + czyx[c];
        g_bx[b][i][c] = c3[c];
    }
#pragma unroll
    for (int c = 0; c < 3; c++) {
        s3[c] = expf(bboxes[base + (long)(c + 3) * NSP]) * ANCH;
        g_bx[b][i][c + 3] = s3[c];
    }
    float4 L = make_float4(c3[0] - 0.5f * s3[0], c3[1] - 0.5f * s3[1],
                           c3[2] - 0.5f * s3[2], c3[0] + 0.5f * s3[0]);
    float4 H = make_float4(c3[1] + 0.5f * s3[1], c3[2] + 0.5f * s3[2],
                           s3[0] * s3[1] * s3[2], 0.0f);
    ((float4*)g_pb[b][i])[0] = L;
    ((float4*)g_pb[b][i])[1] = H;
}

__global__ void __launch_bounds__(256) k_rankgather(const float* __restrict__ bboxes) {
    int b = blockIdx.y, bx = blockIdx.x;
    int t = threadIdx.x, lane = t & 31, w = t >> 5;
    unsigned cnt  = g_cnt[b];  if (cnt  > CAND)  cnt  = CAND;
    unsigned scnt = g_scnt[b]; if (scnt > STASH) scnt = STASH;

    if (bx < 64) {
        // ---- cand slots: every cand key > every stash key; rank among cand.
        // 64 blocks x 8 warps x 4 slots = 2048 slots.
        __shared__ unsigned long long sc[CAND];
#pragma unroll
        for (int m = 0; m < 8; m++) sc[m * 256 + t] = g_cand[b][m * 256 + t];
        __syncthreads();
#pragma unroll
        for (int s = 0; s < 4; s++) {
            unsigned slot = (unsigned)(bx * 32 + s * 8 + w);
            if (slot < cnt) {
                unsigned long long mine = sc[slot];
                unsigned c = 0;
#pragma unroll 4
                for (unsigned j = lane; j < cnt; j += 32) c += (sc[j] > mine) ? 1u : 0u;
                unsigned rank = __reduce_add_sync(0xffffffffu, c);
                if (lane == 0) emit_box(b, mine, rank, bboxes);
            }
        }
    } else {
        // ---- stash slots: rank = cnt + rank-within-stash. MLP=4 scan.
        const unsigned long long* st = g_stash[b];
        for (unsigned slot = (bx - 64) * 8 + (unsigned)w; slot < scnt; slot += 128) {
            unsigned long long mine = st[slot];
            unsigned c0 = 0, c1 = 0, c2 = 0, c3 = 0;
            unsigned j = lane;
            for (; j + 96 < scnt; j += 128) {
                c0 += (st[j]      > mine) ? 1u : 0u;
                c1 += (st[j + 32] > mine) ? 1u : 0u;
                c2 += (st[j + 64] > mine) ? 1u : 0u;
                c3 += (st[j + 96] > mine) ? 1u : 0u;
            }
            for (; j < scnt; j += 32) c0 += (st[j] > mine) ? 1u : 0u;
            unsigned rank = cnt + __reduce_add_sync(0xffffffffu, c0 + c1 + c2 + c3);
            if (lane == 0) emit_box(b, mine, rank, bboxes);
        }
    }
}

// ---------------- K5: IoU bitmask + replay-state cleanup -------------------
__global__ void __launch_bounds__(128) k_iou() {
    int b = blockIdx.z, rbk = blockIdx.y, cb = blockIdx.x, t = threadIdx.x;
    // cleanup for next graph replay: zero histA + counters
    {
        unsigned flat = ((blockIdx.z * gridDim.y + blockIdx.y) * gridDim.x + blockIdx.x) * 128u + t;
        if (flat < BATCH * NBIN / 2) ((unsigned long long*)g_histA)[flat] = 0ull;
        if (flat < BATCH) { g_cnt[flat] = 0u; g_scnt[flat] = 0u; }
    }
    int row0 = rbk << 8;
    int c0 = cb << 6;
    if (c0 + 63 <= row0) return;                       // tile entirely below diag
    __shared__ float4 scol[64][2];
    { int j = t >> 1, h = t & 1; scol[j][h] = ((const float4*)g_pb[b][c0 + j])[h]; }
    __syncthreads();
    int r1 = row0 + t, r2 = row0 + 128 + t;
    float4 aL = ((const float4*)g_pb[b][r1])[0];
    float4 aH = ((const float4*)g_pb[b][r1])[1];
    float4 bL = ((const float4*)g_pb[b][r2])[0];
    float4 bH = ((const float4*)g_pb[b][r2])[1];
    unsigned a0 = 0u, a1 = 0u, b0 = 0u, b1 = 0u;
#pragma unroll
    for (int j = 0; j < 64; j++) {
        float4 cL = scol[j][0], cH = scol[j][1];
        float e0 = fmaxf(fminf(aL.w, cL.w) - fmaxf(aL.x, cL.x), 0.0f);
        float e1 = fmaxf(fminf(aH.x, cH.x) - fmaxf(aL.y, cL.y), 0.0f);
        float e2 = fmaxf(fminf(aH.y, cH.y) - fmaxf(aL.z, cL.z), 0.0f);
        float inter1 = e0 * e1 * e2;
        bool p1 = (5.0f * inter1 > aH.z + cH.z);
        float f0 = fmaxf(fminf(bL.w, cL.w) - fmaxf(bL.x, cL.x), 0.0f);
        float f1 = fmaxf(fminf(bH.x, cH.x) - fmaxf(bL.y, cL.y), 0.0f);
        float f2 = fmaxf(fminf(bH.y, cH.y) - fmaxf(bL.z, cL.z), 0.0f);
        float inter2 = f0 * f1 * f2;
        bool p2 = (5.0f * inter2 > bH.z + cH.z);
        unsigned bb = 1u << (j & 31);
        if (j < 32) { if (p1) a0 |= bb; if (p2) b0 |= bb; }
        else        { if (p1) a1 |= bb; if (p2) b1 |= bb; }
    }
    unsigned long long bits1 = (unsigned long long)a0 | ((unsigned long long)a1 << 32);
    unsigned long long bits2 = (unsigned long long)b0 | ((unsigned long long)b1 << 32);
    if (c0 + 63 > r1) {
        if (r1 >= c0) { int k = r1 - c0; bits1 &= (~0ull) << (k + 1); }
        g_mask[b][r1][cb] = bits1;
    }
    if (c0 + 63 > r2) {
        if (r2 >= c0) { int k = r2 - c0; bits2 &= (~0ull) << (k + 1); }
        g_mask[b][r2][cb] = bits2;
    }
}

// ---------------- K6: sequential greedy NMS (LDS-broadcast chain) ----------
__global__ void __launch_bounds__(1024) k_nms(float* __restrict__ out) {
    int b = blockIdx.x, tid = threadIdx.x;
    __shared__ unsigned long long s_rows[2][64][32];
    __shared__ unsigned long long s_remv[32];
    unsigned long long remv = 0ull;

    if (tid >= 32) {                                   // preload chunk 0 (64 rows)
        for (int k = tid - 32; k < 2048; k += 992) {
            s_rows[0][k >> 5][k & 31] = g_mask[b][k >> 5][k & 31];
        }
    }
    __syncthreads();

    for (int c = 0; c < 32; c++) {                     // 32 chunks of 64 rows
        int cur = c & 1;
        if (tid >= 32 && c < 31) {
            int nb = cur ^ 1;
            for (int k = tid - 32; k < 2048; k += 992) {
                s_rows[nb][k >> 5][k & 31] = g_mask[b][((c + 1) << 6) + (k >> 5)][k & 31];
            }
        }
        if (tid < 32) {
            unsigned long long local = __shfl_sync(0xffffffffu, remv, c);
#pragma unroll
            for (int rr = 0; rr < 64; rr++) {
                int i = (c << 6) + rr;
                unsigned long long rdat = s_rows[cur][rr][tid];
                unsigned long long rloc = s_rows[cur][rr][c];   // broadcast LDS, off-chain
                if (64 * tid + 63 <= i) rdat = 0ull;            // mask unwritten words
                unsigned long long m =
                    (unsigned long long)((long long)(local << (63 - rr)) >> 63);
                remv |= rdat & ~m;
                local |= rloc & ~m;
            }
        }
        __syncthreads();
    }
    if (tid < 32) s_remv[tid] = remv;
    __syncthreads();

#pragma unroll
    for (int m = 0; m < 2; m++) {
        int i = m * 1024 + tid;
        bool keep = !((s_remv[i >> 6] >> (i & 63)) & 1ull);
        float* o = out + ((long)b * TOPK + i) * 7;
        o[0] = keep ? g_sc[b][i] : 0.0f;
#pragma unroll
        for (int c = 0; c < 6; c++) o[1 + c] = keep ? g_bx[b][i][c] : 0.0f;
    }
}

// ---------------- launch ---------------------------------------------------
extern "C" void kernel_launch(void* const* d_in, const int* in_sizes, int n_in,
                              void* d_out, int out_size) {
    const float* bboxes = (const float*)d_in[0];   // (2,6,64,96,96)
    const float* scores = (const float*)d_in[1];   // (2,64,96,96)
    float* out = (float*)d_out;                    // (2,2048,7)

    k_hist1<<<dim3(144, BATCH), 256>>>(scores);    // full NSP coverage
    k_sel1<<<BATCH, 1024>>>();
    k_pass2<<<dim3(Q4 / 256, BATCH), 256>>>(scores);
    k_rankgather<<<dim3(80, BATCH), 256>>>(bboxes);
    k_iou<<<dim3(32, 8, BATCH), 128>>>();
    k_nms<<<BATCH, 1024>>>(out);
}

// round 11
// speedup vs baseline: 3.8296x; 1.0194x over previous
#include <cuda_runtime.h>
#include <math.h>

#define NSP   589824   // 64*96*96
#define BATCH 2
#define TOPK  2048
#define CAND  2048     // count(prefix > P) < 2048 by construction
#define STASH 16384
#define ANCH  12.0f
#define Q4    36864    // NSP/16
#define NBIN  4096     // 12-bit prefix bins

// ---------------- device scratch (zero-initialized at load; re-zeroed each
// replay by k_iou's cleanup tail so the graph is replay-stable) -------------
__device__ __align__(16) unsigned g_histA[BATCH][NBIN];
__device__ unsigned g_prefix[BATCH];
__device__ unsigned g_cnt[BATCH];
__device__ unsigned g_scnt[BATCH];
__device__ __align__(16) unsigned long long g_cand[BATCH][CAND];
__device__ __align__(16) unsigned long long g_stash[BATCH][STASH];
__device__ float    g_sc[BATCH][TOPK];
__device__ float    g_bx[BATCH][TOPK][6];
__device__ __align__(16) float g_pb[BATCH][TOPK][8];  // lo0,lo1,lo2,hi0 | hi1,hi2,vol,0
__device__ __align__(16) unsigned long long g_mask[BATCH][TOPK][32]; // junk masked in k_nms

__device__ __forceinline__ unsigned fkey(float f) {
    unsigned u = __float_as_uint(f);
    return (u & 0x80000000u) ? ~u : (u | 0x80000000u);
}
__device__ __forceinline__ float fromkey(unsigned k) {
    unsigned u = (k & 0x80000000u) ? (k ^ 0x80000000u) : ~k;
    return __uint_as_float(u);
}

// ---------------- K1: smem-privatized 4096-bin histogram -------------------
__global__ void __launch_bounds__(256) k_hist1(const float* __restrict__ scores) {
    __shared__ unsigned h[NBIN];
    int b = blockIdx.y, t = threadIdx.x;
#pragma unroll
    for (int i = t; i < NBIN; i += 256) h[i] = 0u;
    __syncthreads();
    const float4* p = (const float4*)(scores + (long)b * NSP) + blockIdx.x * 1024;
    float4 v0 = p[t], v1 = p[256 + t], v2 = p[512 + t], v3 = p[768 + t];
    float vv[16] = { v0.x,v0.y,v0.z,v0.w, v1.x,v1.y,v1.z,v1.w,
                     v2.x,v2.y,v2.z,v2.w, v3.x,v3.y,v3.z,v3.w };
#pragma unroll
    for (int q = 0; q < 16; q++) atomicAdd(&h[fkey(vv[q]) >> 20], 1u);
    __syncthreads();
#pragma unroll
    for (int i = t; i < NBIN; i += 256) {
        unsigned c = h[i];
        if (c) atomicAdd(&g_histA[b][i], c);
    }
}

// ---------------- K2: find prefix bin P over 4096 bins ---------------------
__global__ void __launch_bounds__(1024) k_sel1() {
    int b = blockIdx.x;
    __shared__ unsigned warptot[32];
    __shared__ unsigned warpabove[32];
    int t = threadIdx.x, lane = t & 31, wid = t >> 5;
    uint4 v = ((const uint4*)g_histA[b])[t];          // 4 bins per thread
    unsigned local = v.x + v.y + v.z + v.w;
    unsigned suf = local;                             // suffix-incl within warp
#pragma unroll
    for (int off = 1; off < 32; off <<= 1) {
        unsigned x = __shfl_down_sync(0xffffffffu, suf, off);
        if (lane + off < 32) suf += x;
    }
    if (lane == 0) warptot[wid] = suf;
    __syncthreads();
    if (wid == 0) {
        unsigned w = warptot[lane], ws = w;
#pragma unroll
        for (int off = 1; off < 32; off <<= 1) {
            unsigned x = __shfl_down_sync(0xffffffffu, ws, off);
            if (lane + off < 32) ws += x;
        }
        warpabove[lane] = ws - w;                     // strictly above this warp
    }
    __syncthreads();
    unsigned T = warpabove[wid] + (suf - local);      // strictly above my 4 bins
    if (T < TOPK && T + local >= TOPK) {              // unique owner
        unsigned acc = T, P = 0;
        unsigned hv[4] = { v.w, v.z, v.y, v.x };
        int found = 0;
#pragma unroll
        for (int q = 0; q < 4; q++) {
            if (!found) {
                if (acc + hv[q] >= TOPK) { P = (unsigned)(t * 4 + (3 - q)); found = 1; }
                else acc += hv[q];
            }
        }
        g_prefix[b] = P;
    }
}

// ---------------- K3: collect prefix>P to cand; prefix==P to stash ---------
__global__ void k_pass2(const float* __restrict__ scores) {
    int b = blockIdx.y;
    int t = blockIdx.x * blockDim.x + threadIdx.x;        // 0..Q4-1
    unsigned pref = g_prefix[b];
    const float4* p = (const float4*)(scores + (long)b * NSP);
    float4 v[4] = { p[t], p[t + Q4], p[t + 2 * Q4], p[t + 3 * Q4] };
#pragma unroll
    for (int kk = 0; kk < 4; kk++) {
        float vv[4] = { v[kk].x, v[kk].y, v[kk].z, v[kk].w };
#pragma unroll
        for (int q = 0; q < 4; q++) {
            unsigned k = fkey(vv[q]);
            unsigned pp = k >> 20;
            if (pp >= pref) {
                unsigned idx = (unsigned)((t + kk * Q4) * 4 + q);
                unsigned long long pk = ((unsigned long long)k << 32) | (unsigned)(~idx);
                if (pp > pref) {
                    unsigned pos = atomicAdd(&g_cnt[b], 1u);
                    if (pos < CAND) g_cand[b][pos] = pk;
                } else {
                    unsigned sq = atomicAdd(&g_scnt[b], 1u);
                    if (sq < STASH) g_stash[b][sq] = pk;
                }
            }
        }
    }
}

// ---------------- K4: rank + staged parallel gather ------------------------
__device__ __forceinline__ void emit_box(int b, unsigned long long mine, unsigned rank,
                                         const float* __restrict__ bboxes) {
    if (rank >= TOPK) return;
    int i = (int)rank;
    unsigned key = (unsigned)(mine >> 32);
    unsigned idx = ~(unsigned)(mine & 0xFFFFFFFFull);
    g_sc[b][i] = fromkey(key);
    int z = idx / 9216, r = idx % 9216, y = r / 96, x = r % 96;
    long base = (long)b * 6 * NSP + idx;
    float czyx[3] = { (float)z + 0.5f, (float)y + 0.5f, (float)x + 0.5f };
    float c3[3], s3[3];
#pragma unroll
    for (int c = 0; c < 3; c++) {
        c3[c] = bboxes[base + (long)c * NSP] * ANCH + czyx[c];
        g_bx[b][i][c] = c3[c];
    }
#pragma unroll
    for (int c = 0; c < 3; c++) {
        s3[c] = expf(bboxes[base + (long)(c + 3) * NSP]) * ANCH;
        g_bx[b][i][c + 3] = s3[c];
    }
    float4 L = make_float4(c3[0] - 0.5f * s3[0], c3[1] - 0.5f * s3[1],
                           c3[2] - 0.5f * s3[2], c3[0] + 0.5f * s3[0]);
    float4 H = make_float4(c3[1] + 0.5f * s3[1], c3[2] + 0.5f * s3[2],
                           s3[0] * s3[1] * s3[2], 0.0f);
    ((float4*)g_pb[b][i])[0] = L;
    ((float4*)g_pb[b][i])[1] = H;
}

__global__ void __launch_bounds__(256) k_rankgather(const float* __restrict__ bboxes) {
    int b = blockIdx.y, bx = blockIdx.x;
    int t = threadIdx.x, lane = t & 31, w = t >> 5;
    unsigned cnt  = g_cnt[b];  if (cnt  > CAND)  cnt  = CAND;
    unsigned scnt = g_scnt[b]; if (scnt > STASH) scnt = STASH;

    if (bx < 64) {
        // ---- cand region: 64 blocks x 8 warps x 4 slots. Block-wide staging,
        //      then one emit PER THREAD (max MLP on the cold bbox gathers).
        __shared__ unsigned long long sc[CAND];
        __shared__ unsigned long long st_mine[40];
        __shared__ unsigned st_rank[40];
        __shared__ int st_n;
        if (t == 0) st_n = 0;
#pragma unroll
        for (int m = 0; m < 8; m++) {
            unsigned j = (unsigned)(m * 256 + t);
            sc[j] = (j < cnt) ? g_cand[b][j] : 0ull;   // pad 0: compares false
        }
        __syncthreads();
#pragma unroll
        for (int s = 0; s < 4; s++) {
            unsigned slot = (unsigned)(bx * 32 + s * 8 + w);
            if (slot < cnt) {
                unsigned long long mine = sc[slot];
                unsigned c = 0;
#pragma unroll
                for (int j = lane; j < CAND; j += 32) c += (sc[j] > mine) ? 1u : 0u;
                unsigned rank = __reduce_add_sync(0xffffffffu, c);
                if (lane == 0 && rank < TOPK) {
                    int p = atomicAdd(&st_n, 1);
                    st_mine[p] = mine; st_rank[p] = rank;
                }
            }
        }
        __syncthreads();
        int n = st_n;
        if (t < n) emit_box(b, st_mine[t], st_rank[t], bboxes);
    } else {
        // ---- stash region: 16 blocks x 8 warps; per-warp staging then
        //      lane-parallel emits.
        __shared__ unsigned long long sm_mine[8][128];
        __shared__ unsigned sm_rank[8][128];
        const unsigned long long* st = g_stash[b];
        int w_n = 0;
        for (unsigned slot = (bx - 64) * 8 + (unsigned)w; slot < scnt; slot += 128) {
            unsigned long long mine = st[slot];
            unsigned c0 = 0, c1 = 0, c2 = 0, c3 = 0;
            unsigned j = lane;
            for (; j + 96 < scnt; j += 128) {
                c0 += (st[j]      > mine) ? 1u : 0u;
                c1 += (st[j + 32] > mine) ? 1u : 0u;
                c2 += (st[j + 64] > mine) ? 1u : 0u;
                c3 += (st[j + 96] > mine) ? 1u : 0u;
            }
            for (; j < scnt; j += 32) c0 += (st[j] > mine) ? 1u : 0u;
            unsigned rank = cnt + __reduce_add_sync(0xffffffffu, c0 + c1 + c2 + c3);
            if (rank < TOPK) {                          // uniform across warp
                if (lane == 0) { sm_mine[w][w_n] = mine; sm_rank[w][w_n] = rank; }
                w_n++;
            }
        }
        __syncwarp();
        for (int e = lane; e < w_n; e += 32)
            emit_box(b, sm_mine[w][e], sm_rank[w][e], bboxes);
    }
}

// ---------------- K5: IoU bitmask + replay-state cleanup -------------------
__global__ void __launch_bounds__(128) k_iou() {
    int b = blockIdx.z, rbk = blockIdx.y, cb = blockIdx.x, t = threadIdx.x;
    // cleanup for next graph replay: zero histA + counters
    {
        unsigned flat = ((blockIdx.z * gridDim.y + blockIdx.y) * gridDim.x + blockIdx.x) * 128u + t;
        if (flat < BATCH * NBIN / 2) ((unsigned long long*)g_histA)[flat] = 0ull;
        if (flat < BATCH) { g_cnt[flat] = 0u; g_scnt[flat] = 0u; }
    }
    int row0 = rbk << 8;
    int c0 = cb << 6;
    if (c0 + 63 <= row0) return;                       // tile entirely below diag
    __shared__ float4 scol[64][2];
    { int j = t >> 1, h = t & 1; scol[j][h] = ((const float4*)g_pb[b][c0 + j])[h]; }
    __syncthreads();
    int r1 = row0 + t, r2 = row0 + 128 + t;
    float4 aL = ((const float4*)g_pb[b][r1])[0];
    float4 aH = ((const float4*)g_pb[b][r1])[1];
    float4 bL = ((const float4*)g_pb[b][r2])[0];
    float4 bH = ((const float4*)g_pb[b][r2])[1];
    unsigned a0 = 0u, a1 = 0u, b0 = 0u, b1 = 0u;
#pragma unroll
    for (int j = 0; j < 64; j++) {
        float4 cL = scol[j][0], cH = scol[j][1];
        float e0 = fmaxf(fminf(aL.w, cL.w) - fmaxf(aL.x, cL.x), 0.0f);
        float e1 = fmaxf(fminf(aH.x, cH.x) - fmaxf(aL.y, cL.y), 0.0f);
        float e2 = fmaxf(fminf(aH.y, cH.y) - fmaxf(aL.z, cL.z), 0.0f);
        float inter1 = e0 * e1 * e2;
        bool p1 = (5.0f * inter1 > aH.z + cH.z);
        float f0 = fmaxf(fminf(bL.w, cL.w) - fmaxf(bL.x, cL.x), 0.0f);
        float f1 = fmaxf(fminf(bH.x, cH.x) - fmaxf(bL.y, cL.y), 0.0f);
        float f2 = fmaxf(fminf(bH.y, cH.y) - fmaxf(bL.z, cL.z), 0.0f);
        float inter2 = f0 * f1 * f2;
        bool p2 = (5.0f * inter2 > bH.z + cH.z);
        unsigned bb = 1u << (j & 31);
        if (j < 32) { if (p1) a0 |= bb; if (p2) b0 |= bb; }
        else        { if (p1) a1 |= bb; if (p2) b1 |= bb; }
    }
    unsigned long long bits1 = (unsigned long long)a0 | ((unsigned long long)a1 << 32);
    unsigned long long bits2 = (unsigned long long)b0 | ((unsigned long long)b1 << 32);
    if (c0 + 63 > r1) {
        if (r1 >= c0) { int k = r1 - c0; bits1 &= (~0ull) << (k + 1); }
        g_mask[b][r1][cb] = bits1;
    }
    if (c0 + 63 > r2) {
        if (r2 >= c0) { int k = r2 - c0; bits2 &= (~0ull) << (k + 1); }
        g_mask[b][r2][cb] = bits2;
    }
}

// ---------------- K6: sequential greedy NMS (LDS-broadcast chain) ----------
__global__ void __launch_bounds__(1024) k_nms(float* __restrict__ out) {
    int b = blockIdx.x, tid = threadIdx.x;
    __shared__ unsigned long long s_rows[2][64][32];
    __shared__ unsigned long long s_remv[32];
    unsigned long long remv = 0ull;

    if (tid >= 32) {                                   // preload chunk 0 (64 rows)
        for (int k = tid - 32; k < 2048; k += 992) {
            s_rows[0][k >> 5][k & 31] = g_mask[b][k >> 5][k & 31];
        }
    }
    __syncthreads();

    for (int c = 0; c < 32; c++) {                     // 32 chunks of 64 rows
        int cur = c & 1;
        if (tid >= 32 && c < 31) {
            int nb = cur ^ 1;
            for (int k = tid - 32; k < 2048; k += 992) {
                s_rows[nb][k >> 5][k & 31] = g_mask[b][((c + 1) << 6) + (k >> 5)][k & 31];
            }
        }
        if (tid < 32) {
            unsigned long long local = __shfl_sync(0xffffffffu, remv, c);
#pragma unroll
            for (int rr = 0; rr < 64; rr++) {
                int i = (c << 6) + rr;
                unsigned long long rdat = s_rows[cur][rr][tid];
                unsigned long long rloc = s_rows[cur][rr][c];   // broadcast LDS, off-chain
                if (64 * tid + 63 <= i) rdat = 0ull;            // mask unwritten words
                unsigned long long m =
                    (unsigned long long)((long long)(local << (63 - rr)) >> 63);
                remv |= rdat & ~m;
                local |= rloc & ~m;
            }
        }
        __syncthreads();
    }
    if (tid < 32) s_remv[tid] = remv;
    __syncthreads();

#pragma unroll
    for (int m = 0; m < 2; m++) {
        int i = m * 1024 + tid;
        bool keep = !((s_remv[i >> 6] >> (i & 63)) & 1ull);
        float* o = out + ((long)b * TOPK + i) * 7;
        o[0] = keep ? g_sc[b][i] : 0.0f;
#pragma unroll
        for (int c = 0; c < 6; c++) o[1 + c] = keep ? g_bx[b][i][c] : 0.0f;
    }
}

// ---------------- launch ---------------------------------------------------
extern "C" void kernel_launch(void* const* d_in, const int* in_sizes, int n_in,
                              void* d_out, int out_size) {
    const float* bboxes = (const float*)d_in[0];   // (2,6,64,96,96)
    const float* scores = (const float*)d_in[1];   // (2,64,96,96)
    float* out = (float*)d_out;                    // (2,2048,7)

    k_hist1<<<dim3(144, BATCH), 256>>>(scores);    // full NSP coverage
    k_sel1<<<BATCH, 1024>>>();
    k_pass2<<<dim3(Q4 / 256, BATCH), 256>>>(scores);
    k_rankgather<<<dim3(80, BATCH), 256>>>(bboxes);
    k_iou<<<dim3(32, 8, BATCH), 128>>>();
    k_nms<<<BATCH, 1024>>>(out);
}

// round 12
// speedup vs baseline: 3.9287x; 1.0259x over previous
#include <cuda_runtime.h>
#include <math.h>

#define NSP   589824   // 64*96*96
#define BATCH 2
#define TOPK  2048
#define CAND  2048     // count(prefix > P) < 2048 by construction
#define STASH 16384
#define SSTA  2048     // smem-resident stash window
#define ANCH  12.0f
#define Q4    36864    // NSP/16
#define NBIN  4096     // 12-bit prefix bins

// ---------------- device scratch (zero-initialized at load; re-zeroed each
// replay by k_iou's cleanup tail so the graph is replay-stable) -------------
__device__ __align__(16) unsigned g_histA[BATCH][NBIN];
__device__ unsigned g_done[BATCH];
__device__ unsigned g_prefix[BATCH];
__device__ unsigned g_cnt[BATCH];
__device__ unsigned g_scnt[BATCH];
__device__ __align__(16) unsigned long long g_cand[BATCH][CAND];
__device__ __align__(16) unsigned long long g_stash[BATCH][STASH];
__device__ float    g_sc[BATCH][TOPK];
__device__ float    g_bx[BATCH][TOPK][6];
__device__ __align__(16) float g_pb[BATCH][TOPK][8];  // lo0,lo1,lo2,hi0 | hi1,hi2,vol,0
__device__ __align__(16) unsigned long long g_mask[BATCH][TOPK][32]; // junk masked in k_nms

__device__ __forceinline__ unsigned fkey(float f) {
    unsigned u = __float_as_uint(f);
    return (u & 0x80000000u) ? ~u : (u | 0x80000000u);
}
__device__ __forceinline__ float fromkey(unsigned k) {
    unsigned u = (k & 0x80000000u) ? (k ^ 0x80000000u) : ~k;
    return __uint_as_float(u);
}

// ---------------- K1: histogram + fused last-block prefix selection --------
// grid (144, BATCH) x 256 : full NSP coverage
__global__ void __launch_bounds__(256) k_histsel(const float* __restrict__ scores) {
    __shared__ unsigned h[NBIN];
    __shared__ unsigned sh_ticket;
    int b = blockIdx.y, t = threadIdx.x;
#pragma unroll
    for (int i = t; i < NBIN; i += 256) h[i] = 0u;
    __syncthreads();
    const float4* p = (const float4*)(scores + (long)b * NSP) + blockIdx.x * 1024;
    float4 v0 = p[t], v1 = p[256 + t], v2 = p[512 + t], v3 = p[768 + t];
    float vv[16] = { v0.x,v0.y,v0.z,v0.w, v1.x,v1.y,v1.z,v1.w,
                     v2.x,v2.y,v2.z,v2.w, v3.x,v3.y,v3.z,v3.w };
#pragma unroll
    for (int q = 0; q < 16; q++) atomicAdd(&h[fkey(vv[q]) >> 20], 1u);
    __syncthreads();
#pragma unroll
    for (int i = t; i < NBIN; i += 256) {
        unsigned c = h[i];
        if (c) atomicAdd(&g_histA[b][i], c);
    }
    // ---- done-ticket: last block of this batch runs the selection ----
    __threadfence();
    __syncthreads();
    if (t == 0) sh_ticket = atomicAdd(&g_done[b], 1u);
    __syncthreads();
    if (sh_ticket != 143u) return;

    // selection: 256 threads x 16 bins each, suffix counts, find P
    __shared__ unsigned wt[8], wa[8];
    int lane = t & 31, wid = t >> 5;
    const uint4* h4 = (const uint4*)g_histA[b] + t * 4;
    uint4 hv4[4];
    unsigned local = 0;
#pragma unroll
    for (int j = 0; j < 4; j++) {
        hv4[j] = __ldcg(h4 + j);
        local += hv4[j].x + hv4[j].y + hv4[j].z + hv4[j].w;
    }
    unsigned suf = local;                             // suffix-incl within warp
#pragma unroll
    for (int off = 1; off < 32; off <<= 1) {
        unsigned x = __shfl_down_sync(0xffffffffu, suf, off);
        if (lane + off < 32) suf += x;
    }
    if (lane == 0) wt[wid] = suf;
    __syncthreads();
    if (wid == 0 && lane < 8) {
        unsigned w = wt[lane], ws = w;
#pragma unroll
        for (int off = 1; off < 8; off <<= 1) {
            unsigned x = __shfl_down_sync(0xffu, ws, off);
            if (lane + off < 8) ws += x;
        }
        wa[lane] = ws - w;                            // strictly above this warp
    }
    __syncthreads();
    unsigned T = wa[wid] + (suf - local);             // strictly above my 16 bins
    if (T < TOPK && T + local >= TOPK) {              // unique owner
        unsigned acc = T, P = 0;
        int found = 0;
#pragma unroll
        for (int j = 3; j >= 0; j--) {
            unsigned hh[4] = { hv4[j].w, hv4[j].z, hv4[j].y, hv4[j].x };
#pragma unroll
            for (int q = 0; q < 4; q++) {
                if (!found) {
                    if (acc + hh[q] >= TOPK) { P = (unsigned)(t*16 + 4*j + (3-q)); found = 1; }
                    else acc += hh[q];
                }
            }
        }
        g_prefix[b] = P;
    }
}

// ---------------- K2: collect prefix>P to cand; prefix==P to stash ---------
__global__ void k_pass2(const float* __restrict__ scores) {
    int b = blockIdx.y;
    int t = blockIdx.x * blockDim.x + threadIdx.x;        // 0..Q4-1
    unsigned pref = g_prefix[b];
    const float4* p = (const float4*)(scores + (long)b * NSP);
    float4 v[4] = { p[t], p[t + Q4], p[t + 2 * Q4], p[t + 3 * Q4] };
#pragma unroll
    for (int kk = 0; kk < 4; kk++) {
        float vv[4] = { v[kk].x, v[kk].y, v[kk].z, v[kk].w };
#pragma unroll
        for (int q = 0; q < 4; q++) {
            unsigned k = fkey(vv[q]);
            unsigned pp = k >> 20;
            if (pp >= pref) {
                unsigned idx = (unsigned)((t + kk * Q4) * 4 + q);
                unsigned long long pk = ((unsigned long long)k << 32) | (unsigned)(~idx);
                if (pp > pref) {
                    unsigned pos = atomicAdd(&g_cnt[b], 1u);
                    if (pos < CAND) g_cand[b][pos] = pk;
                } else {
                    unsigned sq = atomicAdd(&g_scnt[b], 1u);
                    if (sq < STASH) g_stash[b][sq] = pk;
                }
            }
        }
    }
}

// ---------------- K3: rank + staged parallel gather ------------------------
__device__ __forceinline__ void emit_box(int b, unsigned long long mine, unsigned rank,
                                         const float* __restrict__ bboxes) {
    if (rank >= TOPK) return;
    int i = (int)rank;
    unsigned key = (unsigned)(mine >> 32);
    unsigned idx = ~(unsigned)(mine & 0xFFFFFFFFull);
    g_sc[b][i] = fromkey(key);
    int z = idx / 9216, r = idx % 9216, y = r / 96, x = r % 96;
    long base = (long)b * 6 * NSP + idx;
    float czyx[3] = { (float)z + 0.5f, (float)y + 0.5f, (float)x + 0.5f };
    float c3[3], s3[3];
#pragma unroll
    for (int c = 0; c < 3; c++) {
        c3[c] = bboxes[base + (long)c * NSP] * ANCH + czyx[c];
        g_bx[b][i][c] = c3[c];
    }
#pragma unroll
    for (int c = 0; c < 3; c++) {
        s3[c] = expf(bboxes[base + (long)(c + 3) * NSP]) * ANCH;
        g_bx[b][i][c + 3] = s3[c];
    }
    float4 L = make_float4(c3[0] - 0.5f * s3[0], c3[1] - 0.5f * s3[1],
                           c3[2] - 0.5f * s3[2], c3[0] + 0.5f * s3[0]);
    float4 H = make_float4(c3[1] + 0.5f * s3[1], c3[2] + 0.5f * s3[2],
                           s3[0] * s3[1] * s3[2], 0.0f);
    ((float4*)g_pb[b][i])[0] = L;
    ((float4*)g_pb[b][i])[1] = H;
}

__global__ void __launch_bounds__(256) k_rankgather(const float* __restrict__ bboxes) {
    int b = blockIdx.y, bx = blockIdx.x;
    int t = threadIdx.x, lane = t & 31, w = t >> 5;
    unsigned cnt  = g_cnt[b];  if (cnt  > CAND)  cnt  = CAND;
    unsigned scnt = g_scnt[b]; if (scnt > STASH) scnt = STASH;

    if (bx < 64) {
        // ---- cand region: smem scan, block staging, thread-parallel emits
        __shared__ unsigned long long sc[CAND];
        __shared__ unsigned long long st_mine[40];
        __shared__ unsigned st_rank[40];
        __shared__ int st_n;
        if (t == 0) st_n = 0;
#pragma unroll
        for (int m = 0; m < 8; m++) {
            unsigned j = (unsigned)(m * 256 + t);
            sc[j] = (j < cnt) ? g_cand[b][j] : 0ull;   // pad 0: compares false
        }
        __syncthreads();
#pragma unroll
        for (int s = 0; s < 4; s++) {
            unsigned slot = (unsigned)(bx * 32 + s * 8 + w);
            if (slot < cnt) {
                unsigned long long mine = sc[slot];
                unsigned c = 0;
#pragma unroll
                for (int j = lane; j < CAND; j += 32) c += (sc[j] > mine) ? 1u : 0u;
                unsigned rank = __reduce_add_sync(0xffffffffu, c);
                if (lane == 0 && rank < TOPK) {
                    int p = atomicAdd(&st_n, 1);
                    st_mine[p] = mine; st_rank[p] = rank;
                }
            }
        }
        __syncthreads();
        int n = st_n;
        if (t < n) emit_box(b, st_mine[t], st_rank[t], bboxes);
    } else {
        // ---- stash region: copy stash window to smem, LDS scans -----------
        __shared__ unsigned long long sst[SSTA];
        __shared__ unsigned long long sm_mine[8][128];
        __shared__ unsigned sm_rank[8][128];
        const unsigned long long* st = g_stash[b];
        unsigned ns = scnt < SSTA ? scnt : SSTA;
        for (unsigned j = (unsigned)t; j < ns; j += 256) sst[j] = st[j];
        __syncthreads();
        int w_n = 0;
        for (unsigned slot = (bx - 64) * 8 + (unsigned)w; slot < scnt; slot += 128) {
            unsigned long long mine = st[slot];
            unsigned c0 = 0, c1 = 0, c2 = 0, c3 = 0;
            unsigned j = lane;
            for (; j + 96 < ns; j += 128) {            // smem scan, MLP 4
                c0 += (sst[j]      > mine) ? 1u : 0u;
                c1 += (sst[j + 32] > mine) ? 1u : 0u;
                c2 += (sst[j + 64] > mine) ? 1u : 0u;
                c3 += (sst[j + 96] > mine) ? 1u : 0u;
            }
            for (; j < ns; j += 32) c0 += (sst[j] > mine) ? 1u : 0u;
            for (j = SSTA + lane; j < scnt; j += 32)   // rare overflow tail
                c0 += (st[j] > mine) ? 1u : 0u;
            unsigned rank = cnt + __reduce_add_sync(0xffffffffu, c0 + c1 + c2 + c3);
            if (rank < TOPK) {                          // uniform across warp
                if (lane == 0) { sm_mine[w][w_n] = mine; sm_rank[w][w_n] = rank; }
                w_n++;
            }
        }
        __syncwarp();
        for (int e = lane; e < w_n; e += 32)
            emit_box(b, sm_mine[w][e], sm_rank[w][e], bboxes);
    }
}

// ---------------- K4: IoU bitmask + replay-state cleanup -------------------
__global__ void __launch_bounds__(128) k_iou() {
    int b = blockIdx.z, rbk = blockIdx.y, cb = blockIdx.x, t = threadIdx.x;
    // cleanup for next graph replay: zero histA + counters
    {
        unsigned flat = ((blockIdx.z * gridDim.y + blockIdx.y) * gridDim.x + blockIdx.x) * 128u + t;
        if (flat < BATCH * NBIN / 2) ((unsigned long long*)g_histA)[flat] = 0ull;
        if (flat < BATCH) { g_cnt[flat] = 0u; g_scnt[flat] = 0u; g_done[flat] = 0u; }
    }
    int row0 = rbk << 8;
    int c0 = cb << 6;
    if (c0 + 63 <= row0) return;                       // tile entirely below diag
    __shared__ float4 scol[64][2];
    { int j = t >> 1, h = t & 1; scol[j][h] = ((const float4*)g_pb[b][c0 + j])[h]; }
    __syncthreads();
    int r1 = row0 + t, r2 = row0 + 128 + t;
    float4 aL = ((const float4*)g_pb[b][r1])[0];
    float4 aH = ((const float4*)g_pb[b][r1])[1];
    float4 bL = ((const float4*)g_pb[b][r2])[0];
    float4 bH = ((const float4*)g_pb[b][r2])[1];
    unsigned a0 = 0u, a1 = 0u, b0 = 0u, b1 = 0u;
#pragma unroll
    for (int j = 0; j < 64; j++) {
        float4 cL = scol[j][0], cH = scol[j][1];
        float e0 = fmaxf(fminf(aL.w, cL.w) - fmaxf(aL.x, cL.x), 0.0f);
        float e1 = fmaxf(fminf(aH.x, cH.x) - fmaxf(aL.y, cL.y), 0.0f);
        float e2 = fmaxf(fminf(aH.y, cH.y) - fmaxf(aL.z, cL.z), 0.0f);
        float inter1 = e0 * e1 * e2;
        bool p1 = (5.0f * inter1 > aH.z + cH.z);
        float f0 = fmaxf(fminf(bL.w, cL.w) - fmaxf(bL.x, cL.x), 0.0f);
        float f1 = fmaxf(fminf(bH.x, cH.x) - fmaxf(bL.y, cL.y), 0.0f);
        float f2 = fmaxf(fminf(bH.y, cH.y) - fmaxf(bL.z, cL.z), 0.0f);
        float inter2 = f0 * f1 * f2;
        bool p2 = (5.0f * inter2 > bH.z + cH.z);
        unsigned bb = 1u << (j & 31);
        if (j < 32) { if (p1) a0 |= bb; if (p2) b0 |= bb; }
        else        { if (p1) a1 |= bb; if (p2) b1 |= bb; }
    }
    unsigned long long bits1 = (unsigned long long)a0 | ((unsigned long long)a1 << 32);
    unsigned long long bits2 = (unsigned long long)b0 | ((unsigned long long)b1 << 32);
    if (c0 + 63 > r1) {
        if (r1 >= c0) { int k = r1 - c0; bits1 &= (~0ull) << (k + 1); }
        g_mask[b][r1][cb] = bits1;
    }
    if (c0 + 63 > r2) {
        if (r2 >= c0) { int k = r2 - c0; bits2 &= (~0ull) << (k + 1); }
        g_mask[b][r2][cb] = bits2;
    }
}

// ---------------- K5: sequential greedy NMS (LDS-broadcast chain) ----------
__global__ void __launch_bounds__(1024) k_nms(float* __restrict__ out) {
    int b = blockIdx.x, tid = threadIdx.x;
    __shared__ unsigned long long s_rows[2][64][32];
    __shared__ unsigned long long s_remv[32];
    unsigned long long remv = 0ull;

    if (tid >= 32) {                                   // preload chunk 0 (64 rows)
        for (int k = tid - 32; k < 2048; k += 992) {
            s_rows[0][k >> 5][k & 31] = g_mask[b][k >> 5][k & 31];
        }
    }
    __syncthreads();

    for (int c = 0; c < 32; c++) {                     // 32 chunks of 64 rows
        int cur = c & 1;
        if (tid >= 32 && c < 31) {
            int nb = cur ^ 1;
            for (int k = tid - 32; k < 2048; k += 992) {
                s_rows[nb][k >> 5][k & 31] = g_mask[b][((c + 1) << 6) + (k >> 5)][k & 31];
            }
        }
        if (tid < 32) {
            unsigned long long local = __shfl_sync(0xffffffffu, remv, c);
#pragma unroll
            for (int rr = 0; rr < 64; rr++) {
                int i = (c << 6) + rr;
                unsigned long long rdat = s_rows[cur][rr][tid];
                unsigned long long rloc = s_rows[cur][rr][c];   // broadcast LDS, off-chain
                if (64 * tid + 63 <= i) rdat = 0ull;            // mask unwritten words
                unsigned long long m =
                    (unsigned long long)((long long)(local << (63 - rr)) >> 63);
                remv |= rdat & ~m;
                local |= rloc & ~m;
            }
        }
        __syncthreads();
    }
    if (tid < 32) s_remv[tid] = remv;
    __syncthreads();

#pragma unroll
    for (int m = 0; m < 2; m++) {
        int i = m * 1024 + tid;
        bool keep = !((s_remv[i >> 6] >> (i & 63)) & 1ull);
        float* o = out + ((long)b * TOPK + i) * 7;
        o[0] = keep ? g_sc[b][i] : 0.0f;
#pragma unroll
        for (int c = 0; c < 6; c++) o[1 + c] = keep ? g_bx[b][i][c] : 0.0f;
    }
}

// ---------------- launch ---------------------------------------------------
extern "C" void kernel_launch(void* const* d_in, const int* in_sizes, int n_in,
                              void* d_out, int out_size) {
    const float* bboxes = (const float*)d_in[0];   // (2,6,64,96,96)
    const float* scores = (const float*)d_in[1];   // (2,64,96,96)
    float* out = (float*)d_out;                    // (2,2048,7)

    k_histsel<<<dim3(144, BATCH), 256>>>(scores);  // hist + fused selection
    k_pass2<<<dim3(Q4 / 256, BATCH), 256>>>(scores);
    k_rankgather<<<dim3(80, BATCH), 256>>>(bboxes);
    k_iou<<<dim3(32, 8, BATCH), 128>>>();
    k_nms<<<BATCH, 1024>>>(out);
}

// round 13
// speedup vs baseline: 4.0315x; 1.0262x over previous
#include <cuda_runtime.h>
#include <math.h>

#define NSP   589824   // 64*96*96
#define BATCH 2
#define TOPK  2048
#define CAND  2048     // count(prefix > P) < 2048 by construction
#define STASH 16384
#define SSTA  2048     // smem-resident stash window
#define ANCH  12.0f
#define NBIN  4096     // 12-bit prefix bins

// ---------------- device scratch (zero-initialized at load; re-zeroed each
// replay by k_iou's cleanup tail so the graph is replay-stable) -------------
__device__ __align__(16) unsigned g_histA[BATCH][NBIN];
__device__ unsigned g_arrive[BATCH];
__device__ unsigned g_cnt[BATCH];
__device__ unsigned g_scnt[BATCH];
__device__ __align__(16) unsigned long long g_cand[BATCH][CAND];
__device__ __align__(16) unsigned long long g_stash[BATCH][STASH];
__device__ float    g_sc[BATCH][TOPK];
__device__ float    g_bx[BATCH][TOPK][6];
__device__ __align__(16) float g_pb[BATCH][TOPK][8];  // lo0,lo1,lo2,hi0 | hi1,hi2,vol,0
__device__ __align__(16) unsigned long long g_mask[BATCH][TOPK][32]; // junk masked in k_nms

__device__ __forceinline__ unsigned fkey(float f) {
    unsigned u = __float_as_uint(f);
    return (u & 0x80000000u) ? ~u : (u | 0x80000000u);
}
__device__ __forceinline__ float fromkey(unsigned k) {
    unsigned u = (k & 0x80000000u) ? (k ^ 0x80000000u) : ~k;
    return __uint_as_float(u);
}

// ---------------- K1: fused hist + spin-barrier + select + collect ---------
// grid (144, BATCH) x 256. All 288 blocks are wave-1 resident (2+ blocks/SM),
// so the arrive-counter spin barrier is deadlock-free.
__global__ void __launch_bounds__(256) k_topk(const float* __restrict__ scores) {
    __shared__ unsigned h[NBIN];
    __shared__ unsigned sh_P;
    __shared__ unsigned wt[8], wa[8];
    int b = blockIdx.y, t = threadIdx.x;
#pragma unroll
    for (int i = t; i < NBIN; i += 256) h[i] = 0u;
    __syncthreads();
    // ---- phase 1: histogram; keys stay live in registers ----
    const float4* p = (const float4*)(scores + (long)b * NSP) + blockIdx.x * 1024;
    float4 v0 = p[t], v1 = p[256 + t], v2 = p[512 + t], v3 = p[768 + t];
    unsigned key[16];
    {
        float vv[16] = { v0.x,v0.y,v0.z,v0.w, v1.x,v1.y,v1.z,v1.w,
                         v2.x,v2.y,v2.z,v2.w, v3.x,v3.y,v3.z,v3.w };
#pragma unroll
        for (int q = 0; q < 16; q++) {
            key[q] = fkey(vv[q]);
            atomicAdd(&h[key[q] >> 20], 1u);
        }
    }
    __syncthreads();
#pragma unroll
    for (int i = t; i < NBIN; i += 256) {
        unsigned c = h[i];
        if (c) atomicAdd(&g_histA[b][i], c);
    }
    // ---- resident-grid barrier (per batch: 144 blocks) ----
    __threadfence();
    __syncthreads();
    if (t == 0) {
        atomicAdd(&g_arrive[b], 1u);
        while (((volatile unsigned*)g_arrive)[b] < 144u) __nanosleep(64);
    }
    __syncthreads();
    // ---- phase 2: selection (redundant per block, L2-hot 16KB) ----
    int lane = t & 31, wid = t >> 5;
    const uint4* h4 = (const uint4*)g_histA[b] + t * 4;
    uint4 hv4[4];
    unsigned local = 0;
#pragma unroll
    for (int j = 0; j < 4; j++) {
        hv4[j] = __ldcg(h4 + j);
        local += hv4[j].x + hv4[j].y + hv4[j].z + hv4[j].w;
    }
    unsigned suf = local;
#pragma unroll
    for (int off = 1; off < 32; off <<= 1) {
        unsigned x = __shfl_down_sync(0xffffffffu, suf, off);
        if (lane + off < 32) suf += x;
    }
    if (lane == 0) wt[wid] = suf;
    __syncthreads();
    if (wid == 0 && lane < 8) {
        unsigned w = wt[lane], ws = w;
#pragma unroll
        for (int off = 1; off < 8; off <<= 1) {
            unsigned x = __shfl_down_sync(0xffu, ws, off);
            if (lane + off < 8) ws += x;
        }
        wa[lane] = ws - w;
    }
    __syncthreads();
    unsigned T = wa[wid] + (suf - local);
    if (T < TOPK && T + local >= TOPK) {               // unique owner in block
        unsigned acc = T, P = 0;
        int found = 0;
#pragma unroll
        for (int j = 3; j >= 0; j--) {
            unsigned hh[4] = { hv4[j].w, hv4[j].z, hv4[j].y, hv4[j].x };
#pragma unroll
            for (int q = 0; q < 4; q++) {
                if (!found) {
                    if (acc + hh[q] >= TOPK) { P = (unsigned)(t*16 + 4*j + (3-q)); found = 1; }
                    else acc += hh[q];
                }
            }
        }
        sh_P = P;
    }
    __syncthreads();
    unsigned pref = sh_P;
    // ---- phase 3: collect from live registers (no re-read of scores) ----
#pragma unroll
    for (int q = 0; q < 16; q++) {
        unsigned k = key[q];
        unsigned pp = k >> 20;
        if (pp >= pref) {
            unsigned idx = (unsigned)((blockIdx.x * 1024 + (q >> 2) * 256 + t) * 4 + (q & 3));
            unsigned long long pk = ((unsigned long long)k << 32) | (unsigned)(~idx);
            if (pp > pref) {
                unsigned pos = atomicAdd(&g_cnt[b], 1u);
                if (pos < CAND) g_cand[b][pos] = pk;
            } else {
                unsigned sq = atomicAdd(&g_scnt[b], 1u);
                if (sq < STASH) g_stash[b][sq] = pk;
            }
        }
    }
}

// ---------------- K2: rank + staged parallel gather ------------------------
__device__ __forceinline__ void emit_box(int b, unsigned long long mine, unsigned rank,
                                         const float* __restrict__ bboxes) {
    if (rank >= TOPK) return;
    int i = (int)rank;
    unsigned key = (unsigned)(mine >> 32);
    unsigned idx = ~(unsigned)(mine & 0xFFFFFFFFull);
    g_sc[b][i] = fromkey(key);
    int z = idx / 9216, r = idx % 9216, y = r / 96, x = r % 96;
    long base = (long)b * 6 * NSP + idx;
    float czyx[3] = { (float)z + 0.5f, (float)y + 0.5f, (float)x + 0.5f };
    float c3[3], s3[3];
#pragma unroll
    for (int c = 0; c < 3; c++) {
        c3[c] = bboxes[base + (long)c * NSP] * ANCH + czyx[c];
        g_bx[b][i][c] = c3[c];
    }
#pragma unroll
    for (int c = 0; c < 3; c++) {
        s3[c] = expf(bboxes[base + (long)(c + 3) * NSP]) * ANCH;
        g_bx[b][i][c + 3] = s3[c];
    }
    float4 L = make_float4(c3[0] - 0.5f * s3[0], c3[1] - 0.5f * s3[1],
                           c3[2] - 0.5f * s3[2], c3[0] + 0.5f * s3[0]);
    float4 H = make_float4(c3[1] + 0.5f * s3[1], c3[2] + 0.5f * s3[2],
                           s3[0] * s3[1] * s3[2], 0.0f);
    ((float4*)g_pb[b][i])[0] = L;
    ((float4*)g_pb[b][i])[1] = H;
}

__global__ void __launch_bounds__(256) k_rankgather(const float* __restrict__ bboxes) {
    int b = blockIdx.y, bx = blockIdx.x;
    int t = threadIdx.x, lane = t & 31, w = t >> 5;
    unsigned cnt  = g_cnt[b];  if (cnt  > CAND)  cnt  = CAND;
    unsigned scnt = g_scnt[b]; if (scnt > STASH) scnt = STASH;

    if (bx < 64) {
        __shared__ unsigned long long sc[CAND];
        __shared__ unsigned long long st_mine[40];
        __shared__ unsigned st_rank[40];
        __shared__ int st_n;
        if (t == 0) st_n = 0;
#pragma unroll
        for (int m = 0; m < 8; m++) {
            unsigned j = (unsigned)(m * 256 + t);
            sc[j] = (j < cnt) ? g_cand[b][j] : 0ull;   // pad 0: compares false
        }
        __syncthreads();
#pragma unroll
        for (int s = 0; s < 4; s++) {
            unsigned slot = (unsigned)(bx * 32 + s * 8 + w);
            if (slot < cnt) {
                unsigned long long mine = sc[slot];
                unsigned c = 0;
#pragma unroll
                for (int j = lane; j < CAND; j += 32) c += (sc[j] > mine) ? 1u : 0u;
                unsigned rank = __reduce_add_sync(0xffffffffu, c);
                if (lane == 0 && rank < TOPK) {
                    int p = atomicAdd(&st_n, 1);
                    st_mine[p] = mine; st_rank[p] = rank;
                }
            }
        }
        __syncthreads();
        int n = st_n;
        if (t < n) emit_box(b, st_mine[t], st_rank[t], bboxes);
    } else {
        __shared__ unsigned long long sst[SSTA];
        __shared__ unsigned long long sm_mine[8][128];
        __shared__ unsigned sm_rank[8][128];
        const unsigned long long* st = g_stash[b];
        unsigned ns = scnt < SSTA ? scnt : SSTA;
        for (unsigned j = (unsigned)t; j < ns; j += 256) sst[j] = st[j];
        __syncthreads();
        int w_n = 0;
        for (unsigned slot = (bx - 64) * 8 + (unsigned)w; slot < scnt; slot += 128) {
            unsigned long long mine = st[slot];
            unsigned c0 = 0, c1 = 0, c2 = 0, c3 = 0;
            unsigned j = lane;
            for (; j + 96 < ns; j += 128) {
                c0 += (sst[j]      > mine) ? 1u : 0u;
                c1 += (sst[j + 32] > mine) ? 1u : 0u;
                c2 += (sst[j + 64] > mine) ? 1u : 0u;
                c3 += (sst[j + 96] > mine) ? 1u : 0u;
            }
            for (; j < ns; j += 32) c0 += (sst[j] > mine) ? 1u : 0u;
            for (j = SSTA + lane; j < scnt; j += 32)
                c0 += (st[j] > mine) ? 1u : 0u;
            unsigned rank = cnt + __reduce_add_sync(0xffffffffu, c0 + c1 + c2 + c3);
            if (rank < TOPK) {
                if (lane == 0) { sm_mine[w][w_n] = mine; sm_rank[w][w_n] = rank; }
                w_n++;
            }
        }
        __syncwarp();
        for (int e = lane; e < w_n; e += 32)
            emit_box(b, sm_mine[w][e], sm_rank[w][e], bboxes);
    }
}

// ---------------- K3: IoU bitmask + replay-state cleanup -------------------
__global__ void __launch_bounds__(128) k_iou() {
    int b = blockIdx.z, rbk = blockIdx.y, cb = blockIdx.x, t = threadIdx.x;
    // cleanup for next graph replay: zero histA + counters
    {
        unsigned flat = ((blockIdx.z * gridDim.y + blockIdx.y) * gridDim.x + blockIdx.x) * 128u + t;
        if (flat < BATCH * NBIN / 2) ((unsigned long long*)g_histA)[flat] = 0ull;
        if (flat < BATCH) { g_cnt[flat] = 0u; g_scnt[flat] = 0u; g_arrive[flat] = 0u; }
    }
    int row0 = rbk << 8;
    int c0 = cb << 6;
    if (c0 + 63 <= row0) return;                       // tile entirely below diag
    __shared__ float4 scol[64][2];
    { int j = t >> 1, h = t & 1; scol[j][h] = ((const float4*)g_pb[b][c0 + j])[h]; }
    __syncthreads();
    int r1 = row0 + t, r2 = row0 + 128 + t;
    float4 aL = ((const float4*)g_pb[b][r1])[0];
    float4 aH = ((const float4*)g_pb[b][r1])[1];
    float4 bL = ((const float4*)g_pb[b][r2])[0];
    float4 bH = ((const float4*)g_pb[b][r2])[1];
    unsigned a0 = 0u, a1 = 0u, b0 = 0u, b1 = 0u;
#pragma unroll
    for (int j = 0; j < 64; j++) {
        float4 cL = scol[j][0], cH = scol[j][1];
        float e0 = fmaxf(fminf(aL.w, cL.w) - fmaxf(aL.x, cL.x), 0.0f);
        float e1 = fmaxf(fminf(aH.x, cH.x) - fmaxf(aL.y, cL.y), 0.0f);
        float e2 = fmaxf(fminf(aH.y, cH.y) - fmaxf(aL.z, cL.z), 0.0f);
        float inter1 = e0 * e1 * e2;
        bool p1 = (5.0f * inter1 > aH.z + cH.z);
        float f0 = fmaxf(fminf(bL.w, cL.w) - fmaxf(bL.x, cL.x), 0.0f);
        float f1 = fmaxf(fminf(bH.x, cH.x) - fmaxf(bL.y, cL.y), 0.0f);
        float f2 = fmaxf(fminf(bH.y, cH.y) - fmaxf(bL.z, cL.z), 0.0f);
        float inter2 = f0 * f1 * f2;
        bool p2 = (5.0f * inter2 > bH.z + cH.z);
        unsigned bb = 1u << (j & 31);
        if (j < 32) { if (p1) a0 |= bb; if (p2) b0 |= bb; }
        else        { if (p1) a1 |= bb; if (p2) b1 |= bb; }
    }
    unsigned long long bits1 = (unsigned long long)a0 | ((unsigned long long)a1 << 32);
    unsigned long long bits2 = (unsigned long long)b0 | ((unsigned long long)b1 << 32);
    if (c0 + 63 > r1) {
        if (r1 >= c0) { int k = r1 - c0; bits1 &= (~0ull) << (k + 1); }
        g_mask[b][r1][cb] = bits1;
    }
    if (c0 + 63 > r2) {
        if (r2 >= c0) { int k = r2 - c0; bits2 &= (~0ull) << (k + 1); }
        g_mask[b][r2][cb] = bits2;
    }
}

// ---------------- K4: sequential greedy NMS (LDS-broadcast chain) ----------
__global__ void __launch_bounds__(1024) k_nms(float* __restrict__ out) {
    int b = blockIdx.x, tid = threadIdx.x;
    __shared__ unsigned long long s_rows[2][64][32];
    __shared__ unsigned long long s_remv[32];
    unsigned long long remv = 0ull;

    if (tid >= 32) {                                   // preload chunk 0 (64 rows)
        for (int k = tid - 32; k < 2048; k += 992) {
            s_rows[0][k >> 5][k & 31] = g_mask[b][k >> 5][k & 31];
        }
    }
    __syncthreads();

    for (int c = 0; c < 32; c++) {                     // 32 chunks of 64 rows
        int cur = c & 1;
        if (tid >= 32 && c < 31) {
            int nb = cur ^ 1;
            for (int k = tid - 32; k < 2048; k += 992) {
                s_rows[nb][k >> 5][k & 31] = g_mask[b][((c + 1) << 6) + (k >> 5)][k & 31];
            }
        }
        if (tid < 32) {
            unsigned long long local = __shfl_sync(0xffffffffu, remv, c);
#pragma unroll
            for (int rr = 0; rr < 64; rr++) {
                int i = (c << 6) + rr;
                unsigned long long rdat = s_rows[cur][rr][tid];
                unsigned long long rloc = s_rows[cur][rr][c];   // broadcast LDS, off-chain
                if (64 * tid + 63 <= i) rdat = 0ull;            // mask unwritten words
                unsigned long long m =
                    (unsigned long long)((long long)(local << (63 - rr)) >> 63);
                remv |= rdat & ~m;
                local |= rloc & ~m;
            }
        }
        __syncthreads();
    }
    if (tid < 32) s_remv[tid] = remv;
    __syncthreads();

#pragma unroll
    for (int m = 0; m < 2; m++) {
        int i = m * 1024 + tid;
        bool keep = !((s_remv[i >> 6] >> (i & 63)) & 1ull);
        float* o = out + ((long)b * TOPK + i) * 7;
        o[0] = keep ? g_sc[b][i] : 0.0f;
#pragma unroll
        for (int c = 0; c < 6; c++) o[1 + c] = keep ? g_bx[b][i][c] : 0.0f;
    }
}

// ---------------- launch ---------------------------------------------------
extern "C" void kernel_launch(void* const* d_in, const int* in_sizes, int n_in,
                              void* d_out, int out_size) {
    const float* bboxes = (const float*)d_in[0];   // (2,6,64,96,96)
    const float* scores = (const float*)d_in[1];   // (2,64,96,96)
    float* out = (float*)d_out;                    // (2,2048,7)

    k_topk<<<dim3(144, BATCH), 256>>>(scores);     // hist+select+collect fused
    k_rankgather<<<dim3(80, BATCH), 256>>>(bboxes);
    k_iou<<<dim3(32, 8, BATCH), 128>>>();
    k_nms<<<BATCH, 1024>>>(out);
}